// round 13
// baseline (speedup 1.0000x reference)
#include <cuda_runtime.h>
#include <cuda_bf16.h>
#include <cstdint>

// ---------------------------------------------------------------------------
// GCN1: 3x (GCNConv -> BatchNorm -> ReLU[except last]) on N=100000, E=800000
// Output: concat( out[N x 40], x6[N x 512] )
//
// Pipeline (aggregate on the narrow side; GEMMs via mma.sync bf16-split):
//   L1: u = agg(x)[128]   -> h = uW1+b1 -> BN+ReLU -> x3
//   L2: u = agg(x3)[512]  -> h = uW2+b2 -> BN+ReLU -> x6 (+bf16 split)
//   L3: h = x6W3 [40]     -> y = agg(h)+b3 -> BN   -> out
// GEMM numerics: A,B split into bf16 (hi, lo); acc += Ah*Bh + Ah*Bl + Al*Bh
// in fp32 (dropped ll term ~2^-16).
// ---------------------------------------------------------------------------

#define NODES_MAX 100000
#define EDGES_MAX 800000
#define HID 512

// ---- device scratch ----
__device__ __nv_bfloat16 g_uh[NODES_MAX * HID];
__device__ __nv_bfloat16 g_ul[NODES_MAX * HID];
__device__ float  g_h [NODES_MAX * HID];
__device__ float  g_t [NODES_MAX * HID];
__device__ __nv_bfloat16 g_wh[HID * HID];   // transposed: [nb][K]
__device__ __nv_bfloat16 g_wl[HID * HID];
__device__ float  g_dinv[NODES_MAX];
__device__ int    g_deg[NODES_MAX];
__device__ int    g_rowptr[NODES_MAX + 1];
__device__ int    g_cursor[NODES_MAX];
__device__ int    g_csrsrc[EDGES_MAX];
__device__ int    g_bsums[256];
__device__ double g_stats[2 * HID];
__device__ float  g_scale[HID];
__device__ float  g_shift[HID];
__device__ int    g_is64;

__device__ __forceinline__ void split_bf16(float v, __nv_bfloat16& h, __nv_bfloat16& l) {
    h = __float2bfloat16(v);
    l = __float2bfloat16(v - __bfloat162float(h));
}

// mma.sync m16n8k16 bf16 x bf16 -> f32 (PTX ISA 7.0, sm_80+, no 'a' features)
__device__ __forceinline__ void mma_bf16(float (&c)[4],
                                         const uint32_t (&a)[4],
                                         const uint32_t (&b)[2]) {
    asm volatile(
        "mma.sync.aligned.m16n8k16.row.col.f32.bf16.bf16.f32 "
        "{%0,%1,%2,%3}, {%4,%5,%6,%7}, {%8,%9}, {%0,%1,%2,%3};"
        : "+f"(c[0]), "+f"(c[1]), "+f"(c[2]), "+f"(c[3])
        : "r"(a[0]), "r"(a[1]), "r"(a[2]), "r"(a[3]), "r"(b[0]), "r"(b[1]));
}

// ===========================================================================
// Graph prep (CSR by dst, dinv) — proven in round 7
// ===========================================================================
__global__ void detect_k(const long long* __restrict__ p, int cnt, int n) {
    __shared__ int bad;
    if (threadIdx.x == 0) bad = 0;
    __syncthreads();
    int loc = 0;
    for (int i = threadIdx.x; i < cnt; i += blockDim.x) {
        long long v = p[i];
        if (v < 0 || v >= (long long)n) loc = 1;
    }
    if (loc) bad = 1;
    __syncthreads();
    if (threadIdx.x == 0) g_is64 = bad ? 0 : 1;
}
__global__ void zero_deg_k(int n) {
    int i = blockIdx.x * blockDim.x + threadIdx.x;
    if (i < n) g_deg[i] = 0;
}
__global__ void hist_k(const void* __restrict__ ei, int E) {
    int e = blockIdx.x * blockDim.x + threadIdx.x;
    if (e >= E) return;
    int d;
    if (g_is64) d = (int)((const long long*)ei)[(size_t)E + e];
    else        d = ((const int*)ei)[(size_t)E + e];
    atomicAdd(&g_deg[d], 1);
}
__global__ void dinv_k(int n) {
    int i = blockIdx.x * blockDim.x + threadIdx.x;
    if (i < n) g_dinv[i] = rsqrtf((float)g_deg[i] + 1.0f);
}
__global__ void scan1_k(int n) {
    __shared__ int sh[1024];
    int tid = threadIdx.x;
    int i = blockIdx.x * 1024 + tid;
    int v = (i < n) ? g_deg[i] : 0;
    sh[tid] = v;
    __syncthreads();
    for (int off = 1; off < 1024; off <<= 1) {
        int t = 0;
        if (tid >= off) t = sh[tid - off];
        __syncthreads();
        sh[tid] += t;
        __syncthreads();
    }
    if (i < n) g_rowptr[i] = sh[tid] - v;
    if (tid == 1023) g_bsums[blockIdx.x] = sh[1023];
}
__global__ void scan2_k(int nb) {
    if (threadIdx.x == 0 && blockIdx.x == 0) {
        int acc = 0;
        for (int i = 0; i < nb; i++) { int t = g_bsums[i]; g_bsums[i] = acc; acc += t; }
    }
}
__global__ void scan3_k(int n, int E) {
    int i = blockIdx.x * blockDim.x + threadIdx.x;
    if (i < n) {
        int r = g_rowptr[i] + g_bsums[i >> 10];
        g_rowptr[i] = r;
        g_cursor[i] = r;
    }
    if (i == 0) g_rowptr[n] = E;
}
__global__ void fill_k(const void* __restrict__ ei, int E) {
    int e = blockIdx.x * blockDim.x + threadIdx.x;
    if (e >= E) return;
    int s, d;
    if (g_is64) {
        const long long* p = (const long long*)ei;
        s = (int)p[e]; d = (int)p[(size_t)E + e];
    } else {
        const int* p = (const int*)ei;
        s = p[e]; d = p[(size_t)E + e];
    }
    int pos = atomicAdd(&g_cursor[d], 1);
    g_csrsrc[pos] = s;
}

// ===========================================================================
// Weight convert: g_wh/g_wl[nb*K+k] = split( W[k*N+nb] ), zero-pad nb>=N
// (transposed layout = exactly the mma.sync "col" B operand, K contiguous)
// ===========================================================================
__global__ void wconv_k(const float* __restrict__ W, int K, int N, int NB) {
    int i = blockIdx.x * blockDim.x + threadIdx.x;
    if (i >= NB * K) return;
    int nb = i / K, k = i - nb * K;
    float v = (nb < N) ? W[(size_t)k * N + nb] : 0.0f;
    __nv_bfloat16 h, l;
    split_bf16(v, h, l);
    g_wh[i] = h;
    g_wl[i] = l;
}

// ===========================================================================
// Aggregation (CSR gather): u_d = dinv_d * ( sum_e dinv_s*in_s + dinv_d*in_d )
// Variant A: emits bf16 hi/lo (GEMM operand). Variant B: fp32 + bias (L3).
// ===========================================================================
__global__ void agg_split_k(const float* __restrict__ in,
                            __nv_bfloat16* __restrict__ oh,
                            __nv_bfloat16* __restrict__ ol, int F4) {
    int node = blockIdx.x;
    int tid = threadIdx.x;
    if (tid >= F4) return;
    const float4* iv = (const float4*)in;
    float dd = g_dinv[node];
    float4 sv = __ldg(&iv[(size_t)node * F4 + tid]);
    float4 acc = make_float4(sv.x * dd, sv.y * dd, sv.z * dd, sv.w * dd);
    int e = g_rowptr[node], e1 = g_rowptr[node + 1];
    for (; e + 1 < e1; e += 2) {
        int s0 = g_csrsrc[e], s1 = g_csrsrc[e + 1];
        float d0 = g_dinv[s0], d1 = g_dinv[s1];
        float4 v0 = __ldg(&iv[(size_t)s0 * F4 + tid]);
        float4 v1 = __ldg(&iv[(size_t)s1 * F4 + tid]);
        acc.x += v0.x * d0 + v1.x * d1;
        acc.y += v0.y * d0 + v1.y * d1;
        acc.z += v0.z * d0 + v1.z * d1;
        acc.w += v0.w * d0 + v1.w * d1;
    }
    if (e < e1) {
        int s = g_csrsrc[e];
        float ds = g_dinv[s];
        float4 v = __ldg(&iv[(size_t)s * F4 + tid]);
        acc.x += v.x * ds; acc.y += v.y * ds; acc.z += v.z * ds; acc.w += v.w * ds;
    }
    acc.x *= dd; acc.y *= dd; acc.z *= dd; acc.w *= dd;

    __nv_bfloat16 h0, l0, h1, l1, h2, l2, h3, l3;
    split_bf16(acc.x, h0, l0); split_bf16(acc.y, h1, l1);
    split_bf16(acc.z, h2, l2); split_bf16(acc.w, h3, l3);
    size_t base = ((size_t)node * F4 + tid) * 4;
    uint2 ph, pl;
    ph.x = (uint32_t)__bfloat16_as_ushort(h0) | ((uint32_t)__bfloat16_as_ushort(h1) << 16);
    ph.y = (uint32_t)__bfloat16_as_ushort(h2) | ((uint32_t)__bfloat16_as_ushort(h3) << 16);
    pl.x = (uint32_t)__bfloat16_as_ushort(l0) | ((uint32_t)__bfloat16_as_ushort(l1) << 16);
    pl.y = (uint32_t)__bfloat16_as_ushort(l2) | ((uint32_t)__bfloat16_as_ushort(l3) << 16);
    *(uint2*)(oh + base) = ph;
    *(uint2*)(ol + base) = pl;
}

__global__ void agg_f32_k(const float* __restrict__ in, float* __restrict__ out,
                          const float* __restrict__ bias, int F4) {
    int node = blockIdx.x;
    int tid = threadIdx.x;
    if (tid >= F4) return;
    const float4* iv = (const float4*)in;
    float dd = g_dinv[node];
    float4 sv = __ldg(&iv[(size_t)node * F4 + tid]);
    float4 acc = make_float4(sv.x * dd, sv.y * dd, sv.z * dd, sv.w * dd);
    int e = g_rowptr[node], e1 = g_rowptr[node + 1];
    for (; e < e1; e++) {
        int s = g_csrsrc[e];
        float ds = g_dinv[s];
        float4 v = __ldg(&iv[(size_t)s * F4 + tid]);
        acc.x += v.x * ds; acc.y += v.y * ds; acc.z += v.z * ds; acc.w += v.w * ds;
    }
    float4 bb = __ldg(&((const float4*)bias)[tid]);
    float4 o;
    o.x = fmaf(acc.x, dd, bb.x);
    o.y = fmaf(acc.y, dd, bb.y);
    o.z = fmaf(acc.z, dd, bb.z);
    o.w = fmaf(acc.w, dd, bb.w);
    ((float4*)out)[(size_t)node * F4 + tid] = o;
}

// ===========================================================================
// Tensor-core GEMM (mma.sync m16n8k16 bf16-split):
//   C[M x NOUT] = A[M x K] @ B^T, B stored [NB x K] (n-major), + bias
// CTA tile: 128 x (NWARPN*32). Warp tile 32x32 (mfrags=2, nfrags=4).
// A staged in smem (pad 72 -> conflict-free lds); B register-direct from L1/L2.
// ===========================================================================
template <int NWARPN>
__global__ void __launch_bounds__(NWARPN * 128, 1) gemm_mma_k(
    const __nv_bfloat16* __restrict__ Ah, const __nv_bfloat16* __restrict__ Al,
    const __nv_bfloat16* __restrict__ Bh, const __nv_bfloat16* __restrict__ Bl,
    float* __restrict__ C, const float* __restrict__ bias,
    int M, int K, int NOUT)
{
    __shared__ __nv_bfloat16 sAh[128][72];
    __shared__ __nv_bfloat16 sAl[128][72];

    const int tid  = threadIdx.x;
    const int lane = tid & 31;
    const int wid  = tid >> 5;
    const int mw   = wid & 3;       // 0..3 (m-warp)
    const int nw   = wid >> 2;      // 0..NWARPN-1 (n-warp)
    const int lq   = lane >> 2;     // 0..7
    const int lr   = lane & 3;      // 0..3
    const int row0 = blockIdx.x * 128;
    const int col0 = blockIdx.y * (NWARPN * 32);

    float acc[2][4][4];
#pragma unroll
    for (int a = 0; a < 2; a++)
#pragma unroll
        for (int b = 0; b < 4; b++)
#pragma unroll
            for (int c = 0; c < 4; c++) acc[a][b][c] = 0.f;

    // per-thread B base pointers (fragment: two bf16 at consecutive k)
    const int bcol = col0 + nw * 32 + lq;
    const __nv_bfloat16* bph = Bh + (size_t)bcol * K + lr * 2;
    const __nv_bfloat16* bpl = Bl + (size_t)bcol * K + lr * 2;

    for (int k0 = 0; k0 < K; k0 += 64) {
        if (k0) __syncthreads();
        // stage A (128 x 64) hi+lo
        for (int s = tid; s < 1024; s += NWARPN * 128) {
            int r = s >> 3, c8 = (s & 7) << 3;
            int gr = row0 + r;
            uint4 vh = make_uint4(0, 0, 0, 0), vl = make_uint4(0, 0, 0, 0);
            if (gr < M) {
                vh = __ldg((const uint4*)(Ah + (size_t)gr * K + k0 + c8));
                vl = __ldg((const uint4*)(Al + (size_t)gr * K + k0 + c8));
            }
            *(uint4*)&sAh[r][c8] = vh;
            *(uint4*)&sAl[r][c8] = vl;
        }
        __syncthreads();

#pragma unroll
        for (int ks = 0; ks < 4; ks++) {
            const int kk = ks * 16;
            uint32_t ah[2][4], al[2][4];
#pragma unroll
            for (int mf = 0; mf < 2; mf++) {
                int r = mw * 32 + mf * 16 + lq;
                int c = kk + lr * 2;
                ah[mf][0] = *(const uint32_t*)&sAh[r][c];
                ah[mf][1] = *(const uint32_t*)&sAh[r + 8][c];
                ah[mf][2] = *(const uint32_t*)&sAh[r][c + 8];
                ah[mf][3] = *(const uint32_t*)&sAh[r + 8][c + 8];
                al[mf][0] = *(const uint32_t*)&sAl[r][c];
                al[mf][1] = *(const uint32_t*)&sAl[r + 8][c];
                al[mf][2] = *(const uint32_t*)&sAl[r][c + 8];
                al[mf][3] = *(const uint32_t*)&sAl[r + 8][c + 8];
            }
#pragma unroll
            for (int nf = 0; nf < 4; nf++) {
                const size_t off = (size_t)nf * 8 * K + k0 + kk;
                uint32_t bh[2], bl[2];
                bh[0] = *(const uint32_t*)(bph + off);
                bh[1] = *(const uint32_t*)(bph + off + 8);
                bl[0] = *(const uint32_t*)(bpl + off);
                bl[1] = *(const uint32_t*)(bpl + off + 8);
#pragma unroll
                for (int mf = 0; mf < 2; mf++) {
                    mma_bf16(acc[mf][nf], ah[mf], bh);   // hh
                    mma_bf16(acc[mf][nf], ah[mf], bl);   // hl
                    mma_bf16(acc[mf][nf], al[mf], bh);   // lh
                }
            }
        }
    }

    // epilogue: + bias, fp32 store (cc even, NOUT even -> float2 safe)
#pragma unroll
    for (int mf = 0; mf < 2; mf++) {
        int r = row0 + mw * 32 + mf * 16 + lq;
#pragma unroll
        for (int nf = 0; nf < 4; nf++) {
            int cc = col0 + nw * 32 + nf * 8 + lr * 2;
            if (cc < NOUT) {
                float2 bb = bias ? *(const float2*)(bias + cc)
                                 : make_float2(0.f, 0.f);
                if (r < M)
                    *(float2*)(C + (size_t)r * NOUT + cc) =
                        make_float2(acc[mf][nf][0] + bb.x, acc[mf][nf][1] + bb.y);
                if (r + 8 < M)
                    *(float2*)(C + (size_t)(r + 8) * NOUT + cc) =
                        make_float2(acc[mf][nf][2] + bb.x, acc[mf][nf][3] + bb.y);
            }
        }
    }
}

// ===========================================================================
// BatchNorm: float partial sums -> double atomics; finalize; apply (+split)
// ===========================================================================
__global__ void zero_stats_k() { g_stats[threadIdx.x] = 0.0; }

__global__ void stats_k(const float* __restrict__ y, int n, int F) {
    int f = threadIdx.x;
    if (f >= F) return;
    float s = 0.f, ss = 0.f;
    for (int r = blockIdx.x; r < n; r += gridDim.x) {
        float v = y[(size_t)r * F + f];
        s += v;
        ss = fmaf(v, v, ss);
    }
    atomicAdd(&g_stats[f], (double)s);
    atomicAdd(&g_stats[F + f], (double)ss);
}

__global__ void finalize_k(const float* __restrict__ gam,
                           const float* __restrict__ bet, int n, int F) {
    int f = threadIdx.x;
    if (f >= F) return;
    double mean = g_stats[f] / (double)n;
    double var  = g_stats[F + f] / (double)n - mean * mean;
    float is = rsqrtf((float)var + 1e-5f);
    float sc = gam[f] * is;
    g_scale[f] = sc;
    g_shift[f] = bet[f] - (float)mean * sc;
}

__global__ void norm_k(const float* __restrict__ y, float* __restrict__ of,
                       __nv_bfloat16* __restrict__ oh, __nv_bfloat16* __restrict__ ol,
                       int F, int do_relu) {
    int node = blockIdx.x;
    for (int f = threadIdx.x; f < F; f += blockDim.x) {
        float v = fmaf(g_scale[f], y[(size_t)node * F + f], g_shift[f]);
        if (do_relu) v = fmaxf(v, 0.0f);
        if (of) of[(size_t)node * F + f] = v;
        if (oh) {
            __nv_bfloat16 h, l;
            split_bf16(v, h, l);
            oh[(size_t)node * F + f] = h;
            ol[(size_t)node * F + f] = l;
        }
    }
}

// ===========================================================================
// host launch
// ===========================================================================
extern "C" void kernel_launch(void* const* d_in, const int* in_sizes, int n_in,
                              void* d_out, int out_size)
{
    const float* x   = (const float*)d_in[0];
    const void*  ei  = d_in[1];
    const float* W1  = (const float*)d_in[2];
    const float* b1  = (const float*)d_in[3];
    const float* ga1 = (const float*)d_in[4];
    const float* be1 = (const float*)d_in[5];
    const float* W2  = (const float*)d_in[6];
    const float* b2  = (const float*)d_in[7];
    const float* ga2 = (const float*)d_in[8];
    const float* be2 = (const float*)d_in[9];
    const float* W3  = (const float*)d_in[10];
    const float* b3  = (const float*)d_in[11];
    const float* ga3 = (const float*)d_in[12];
    const float* be3 = (const float*)d_in[13];

    int n = in_sizes[0] / 128;   // 100000
    int E = in_sizes[1] / 2;     // 800000

    float* out = (float*)d_out;             // [n, 40]
    float* x6  = out + (size_t)n * 40;      // [n, 512]

    __nv_bfloat16 *uh, *ul, *wh, *wl;
    float *hbuf, *tbuf;
    cudaGetSymbolAddress((void**)&uh, g_uh);
    cudaGetSymbolAddress((void**)&ul, g_ul);
    cudaGetSymbolAddress((void**)&wh, g_wh);
    cudaGetSymbolAddress((void**)&wl, g_wl);
    cudaGetSymbolAddress((void**)&hbuf, g_h);
    cudaGetSymbolAddress((void**)&tbuf, g_t);

    const int T = 256;
    int gbN = (n + T - 1) / T;
    int gbE = (E + T - 1) / T;
    int nb1024 = (n + 1023) / 1024;
    int gtiles = (n + 127) / 128;

    // ---- graph prep ----
    detect_k<<<1, 256>>>((const long long*)ei, (E < 4096 ? E : 4096), n);
    zero_deg_k<<<gbN, T>>>(n);
    hist_k<<<gbE, T>>>(ei, E);
    dinv_k<<<gbN, T>>>(n);
    scan1_k<<<nb1024, 1024>>>(n);
    scan2_k<<<1, 32>>>(nb1024);
    scan3_k<<<gbN, T>>>(n, E);
    fill_k<<<gbE, T>>>(ei, E);

    // ---- Layer 1: agg(x)[128] -> GEMM(K=128, N=512) -> BN+ReLU -> tbuf ----
    wconv_k<<<(512 * 128 + 255) / 256, 256>>>(W1, 128, 512, 512);
    agg_split_k<<<n, 32>>>(x, uh, ul, 32);
    gemm_mma_k<4><<<dim3(gtiles, 4), 512>>>(uh, ul, wh, wl, hbuf, b1,
                                            n, 128, 512);
    zero_stats_k<<<1, 1024>>>();
    stats_k<<<256, 512>>>(hbuf, n, 512);
    finalize_k<<<1, 512>>>(ga1, be1, n, 512);
    norm_k<<<n, 128>>>(hbuf, tbuf, nullptr, nullptr, 512, 1);

    // ---- Layer 2: agg(x3)[512] -> GEMM(K=512, N=512) -> BN+ReLU -> x6 ----
    wconv_k<<<(512 * 512 + 255) / 256, 256>>>(W2, 512, 512, 512);
    agg_split_k<<<n, 128>>>(tbuf, uh, ul, 128);
    gemm_mma_k<4><<<dim3(gtiles, 4), 512>>>(uh, ul, wh, wl, hbuf, b2,
                                            n, 512, 512);
    zero_stats_k<<<1, 1024>>>();
    stats_k<<<256, 512>>>(hbuf, n, 512);
    finalize_k<<<1, 512>>>(ga2, be2, n, 512);
    norm_k<<<n, 128>>>(hbuf, x6, uh, ul, 512, 1);

    // ---- Layer 3: GEMM(x6)[K=512, N=40(pad 64)] -> agg(+b3) -> BN -> out ----
    wconv_k<<<(64 * 512 + 255) / 256, 256>>>(W3, 512, 40, 64);
    gemm_mma_k<2><<<dim3(gtiles, 1), 256>>>(uh, ul, wh, wl, tbuf, nullptr,
                                            n, 512, 40);
    agg_f32_k<<<n, 32>>>(tbuf, hbuf, b3, 10);
    zero_stats_k<<<1, 1024>>>();
    stats_k<<<256, 64>>>(hbuf, n, 40);
    finalize_k<<<1, 64>>>(ga3, be3, n, 40);
    norm_k<<<n, 64>>>(hbuf, out, nullptr, nullptr, 40, 0);
}

// round 14
// speedup vs baseline: 1.7812x; 1.7812x over previous
#include <cuda_runtime.h>
#include <cuda_bf16.h>
#include <cstdint>

// ---------------------------------------------------------------------------
// GCN1: 3x (GCNConv -> BatchNorm -> ReLU[except last]) on N=100000, E=800000
// Output: concat( out[N x 40], x6[N x 512] )
//
// Pipeline (aggregate on the narrow side; GEMMs via mma.sync bf16-split):
//   L1: u = agg(x)[128]            -> h1 = uW1+b1 -> BN stats
//   L2: u = agg(relu(bn(h1)))[512] -> h2 = uW2+b2 -> BN -> x6 (+bf16 split)
//   L3: h = x6W3 [40]              -> y = agg(h)+b3 -> BN -> out
// GEMM: A,B split into bf16 (hi,lo); acc += Ah*Bh + Ah*Bl + Al*Bh in fp32.
// GEMM kernel: cp.async double-buffered A+B smem staging, ldmatrix A frags.
// ---------------------------------------------------------------------------

#define NODES_MAX 100000
#define EDGES_MAX 800000
#define HID 512

// ---- device scratch ----
__device__ __nv_bfloat16 g_uh[NODES_MAX * HID];
__device__ __nv_bfloat16 g_ul[NODES_MAX * HID];
__device__ float  g_h [NODES_MAX * HID];
__device__ float  g_t [NODES_MAX * HID];
__device__ __nv_bfloat16 g_wh[HID * HID];   // transposed: [nb][K]
__device__ __nv_bfloat16 g_wl[HID * HID];
__device__ float  g_dinv[NODES_MAX];
__device__ int    g_deg[NODES_MAX];
__device__ int    g_rowptr[NODES_MAX + 1];
__device__ int    g_cursor[NODES_MAX];
__device__ int    g_csrsrc[EDGES_MAX];
__device__ int    g_bsums[256];
__device__ double g_stats[2 * HID];
__device__ float  g_scale[HID];
__device__ float  g_shift[HID];
__device__ int    g_is64;

__device__ __forceinline__ void split_bf16(float v, __nv_bfloat16& h, __nv_bfloat16& l) {
    h = __float2bfloat16(v);
    l = __float2bfloat16(v - __bfloat162float(h));
}

// mma.sync m16n8k16 bf16 x bf16 -> f32 (sm_80 baseline, compute_103-safe)
__device__ __forceinline__ void mma_bf16(float (&c)[4],
                                         const uint32_t (&a)[4],
                                         const uint32_t (&b)[2]) {
    asm volatile(
        "mma.sync.aligned.m16n8k16.row.col.f32.bf16.bf16.f32 "
        "{%0,%1,%2,%3}, {%4,%5,%6,%7}, {%8,%9}, {%0,%1,%2,%3};"
        : "+f"(c[0]), "+f"(c[1]), "+f"(c[2]), "+f"(c[3])
        : "r"(a[0]), "r"(a[1]), "r"(a[2]), "r"(a[3]), "r"(b[0]), "r"(b[1]));
}
__device__ __forceinline__ uint32_t smem_u32(const void* p) {
    uint32_t a;
    asm("{ .reg .u64 t; cvta.to.shared.u64 t, %1; cvt.u32.u64 %0, t; }"
        : "=r"(a) : "l"(p));
    return a;
}
__device__ __forceinline__ void cp16(uint32_t dst, const void* src) {
    asm volatile("cp.async.cg.shared.global [%0], [%1], 16;"
                 :: "r"(dst), "l"(src));
}
__device__ __forceinline__ void ldsm4(uint32_t (&r)[4], uint32_t addr) {
    asm volatile("ldmatrix.sync.aligned.m8n8.x4.shared.b16 {%0,%1,%2,%3}, [%4];"
                 : "=r"(r[0]), "=r"(r[1]), "=r"(r[2]), "=r"(r[3]) : "r"(addr));
}
__device__ __forceinline__ uint32_t lds32(uint32_t addr) {
    uint32_t v;
    asm volatile("ld.shared.b32 %0, [%1];" : "=r"(v) : "r"(addr));
    return v;
}

// ===========================================================================
// Graph prep (CSR by dst, dinv)
// ===========================================================================
__global__ void detect_k(const long long* __restrict__ p, int cnt, int n) {
    __shared__ int bad;
    if (threadIdx.x == 0) bad = 0;
    __syncthreads();
    int loc = 0;
    for (int i = threadIdx.x; i < cnt; i += blockDim.x) {
        long long v = p[i];
        if (v < 0 || v >= (long long)n) loc = 1;
    }
    if (loc) bad = 1;
    __syncthreads();
    if (threadIdx.x == 0) g_is64 = bad ? 0 : 1;
}
__global__ void zero_deg_k(int n) {
    int i = blockIdx.x * blockDim.x + threadIdx.x;
    if (i < n) g_deg[i] = 0;
}
__global__ void hist_k(const void* __restrict__ ei, int E) {
    int e = blockIdx.x * blockDim.x + threadIdx.x;
    if (e >= E) return;
    int d;
    if (g_is64) d = (int)((const long long*)ei)[(size_t)E + e];
    else        d = ((const int*)ei)[(size_t)E + e];
    atomicAdd(&g_deg[d], 1);
}
__global__ void dinv_k(int n) {
    int i = blockIdx.x * blockDim.x + threadIdx.x;
    if (i < n) g_dinv[i] = rsqrtf((float)g_deg[i] + 1.0f);
}
__global__ void scan1_k(int n) {
    __shared__ int sh[1024];
    int tid = threadIdx.x;
    int i = blockIdx.x * 1024 + tid;
    int v = (i < n) ? g_deg[i] : 0;
    sh[tid] = v;
    __syncthreads();
    for (int off = 1; off < 1024; off <<= 1) {
        int t = 0;
        if (tid >= off) t = sh[tid - off];
        __syncthreads();
        sh[tid] += t;
        __syncthreads();
    }
    if (i < n) g_rowptr[i] = sh[tid] - v;
    if (tid == 1023) g_bsums[blockIdx.x] = sh[1023];
}
__global__ void scan2_k(int nb) {
    if (threadIdx.x == 0 && blockIdx.x == 0) {
        int acc = 0;
        for (int i = 0; i < nb; i++) { int t = g_bsums[i]; g_bsums[i] = acc; acc += t; }
    }
}
__global__ void scan3_k(int n, int E) {
    int i = blockIdx.x * blockDim.x + threadIdx.x;
    if (i < n) {
        int r = g_rowptr[i] + g_bsums[i >> 10];
        g_rowptr[i] = r;
        g_cursor[i] = r;
    }
    if (i == 0) g_rowptr[n] = E;
}
__global__ void fill_k(const void* __restrict__ ei, int E) {
    int e = blockIdx.x * blockDim.x + threadIdx.x;
    if (e >= E) return;
    int s, d;
    if (g_is64) {
        const long long* p = (const long long*)ei;
        s = (int)p[e]; d = (int)p[(size_t)E + e];
    } else {
        const int* p = (const int*)ei;
        s = p[e]; d = p[(size_t)E + e];
    }
    int pos = atomicAdd(&g_cursor[d], 1);
    g_csrsrc[pos] = s;
}

// ===========================================================================
// Weight convert: g_wh/g_wl[nb*K+k] = split( W[k*N+nb] ), zero-pad nb>=N
// ===========================================================================
__global__ void wconv_k(const float* __restrict__ W, int K, int N, int NB) {
    int i = blockIdx.x * blockDim.x + threadIdx.x;
    if (i >= NB * K) return;
    int nb = i / K, k = i - nb * K;
    float v = (nb < N) ? W[(size_t)k * N + nb] : 0.0f;
    __nv_bfloat16 h, l;
    split_bf16(v, h, l);
    g_wh[i] = h;
    g_wl[i] = l;
}

// ===========================================================================
// Aggregation (CSR gather), optional fused BN-affine+ReLU on gathered input:
//   u_d = dinv_d * ( sum_e dinv_s * t(in_s) + dinv_d * t(in_d) )
//   t(v) = affine ? relu(scale*v+shift) : v
// Emits bf16 hi/lo split (GEMM A operand). F4 = feature/4, NPB nodes/block.
// ===========================================================================
__device__ __forceinline__ float4 xform(float4 v, float4 sc, float4 sh, int affine) {
    if (affine) {
        v.x = fmaxf(fmaf(sc.x, v.x, sh.x), 0.f);
        v.y = fmaxf(fmaf(sc.y, v.y, sh.y), 0.f);
        v.z = fmaxf(fmaf(sc.z, v.z, sh.z), 0.f);
        v.w = fmaxf(fmaf(sc.w, v.w, sh.w), 0.f);
    }
    return v;
}

template <int F4, int NPB>
__global__ void agg_split_k(const float* __restrict__ in,
                            __nv_bfloat16* __restrict__ oh,
                            __nv_bfloat16* __restrict__ ol,
                            int n, int affine) {
    int sub  = threadIdx.x & (F4 - 1);
    int node = blockIdx.x * NPB + (threadIdx.x / F4);
    if (node >= n) return;
    const float4* iv = (const float4*)in;
    float4 sc = make_float4(1.f, 1.f, 1.f, 1.f);
    float4 sh = make_float4(0.f, 0.f, 0.f, 0.f);
    if (affine) {
        sc = *(const float4*)(g_scale + sub * 4);
        sh = *(const float4*)(g_shift + sub * 4);
    }
    float dd = g_dinv[node];
    float4 v = xform(__ldg(&iv[(size_t)node * F4 + sub]), sc, sh, affine);
    float4 acc = make_float4(v.x * dd, v.y * dd, v.z * dd, v.w * dd);
    int e = g_rowptr[node], e1 = g_rowptr[node + 1];
    for (; e + 1 < e1; e += 2) {
        int s0 = g_csrsrc[e], s1 = g_csrsrc[e + 1];
        float d0 = g_dinv[s0], d1 = g_dinv[s1];
        float4 v0 = xform(__ldg(&iv[(size_t)s0 * F4 + sub]), sc, sh, affine);
        float4 v1 = xform(__ldg(&iv[(size_t)s1 * F4 + sub]), sc, sh, affine);
        acc.x += v0.x * d0 + v1.x * d1;
        acc.y += v0.y * d0 + v1.y * d1;
        acc.z += v0.z * d0 + v1.z * d1;
        acc.w += v0.w * d0 + v1.w * d1;
    }
    if (e < e1) {
        int s = g_csrsrc[e];
        float ds = g_dinv[s];
        float4 vv = xform(__ldg(&iv[(size_t)s * F4 + sub]), sc, sh, affine);
        acc.x += vv.x * ds; acc.y += vv.y * ds;
        acc.z += vv.z * ds; acc.w += vv.w * ds;
    }
    acc.x *= dd; acc.y *= dd; acc.z *= dd; acc.w *= dd;

    __nv_bfloat16 h0, l0, h1, l1, h2, l2, h3, l3;
    split_bf16(acc.x, h0, l0); split_bf16(acc.y, h1, l1);
    split_bf16(acc.z, h2, l2); split_bf16(acc.w, h3, l3);
    size_t base = ((size_t)node * F4 + sub) * 4;
    uint2 ph, pl;
    ph.x = (uint32_t)__bfloat16_as_ushort(h0) | ((uint32_t)__bfloat16_as_ushort(h1) << 16);
    ph.y = (uint32_t)__bfloat16_as_ushort(h2) | ((uint32_t)__bfloat16_as_ushort(h3) << 16);
    pl.x = (uint32_t)__bfloat16_as_ushort(l0) | ((uint32_t)__bfloat16_as_ushort(l1) << 16);
    pl.y = (uint32_t)__bfloat16_as_ushort(l2) | ((uint32_t)__bfloat16_as_ushort(l3) << 16);
    *(uint2*)(oh + base) = ph;
    *(uint2*)(ol + base) = pl;
}

// L3 aggregation, fp32 + bias. F4=10; 16 threads/node, 8 nodes/block.
__global__ void agg_f32_k(const float* __restrict__ in, float* __restrict__ out,
                          const float* __restrict__ bias, int n, int F4) {
    int sub  = threadIdx.x & 15;
    int node = blockIdx.x * 8 + (threadIdx.x >> 4);
    if (node >= n || sub >= F4) return;
    const float4* iv = (const float4*)in;
    float dd = g_dinv[node];
    float4 sv = __ldg(&iv[(size_t)node * F4 + sub]);
    float4 acc = make_float4(sv.x * dd, sv.y * dd, sv.z * dd, sv.w * dd);
    int e = g_rowptr[node], e1 = g_rowptr[node + 1];
    for (; e < e1; e++) {
        int s = g_csrsrc[e];
        float ds = g_dinv[s];
        float4 v = __ldg(&iv[(size_t)s * F4 + sub]);
        acc.x += v.x * ds; acc.y += v.y * ds; acc.z += v.z * ds; acc.w += v.w * ds;
    }
    float4 bb = __ldg(&((const float4*)bias)[sub]);
    float4 o;
    o.x = fmaf(acc.x, dd, bb.x);
    o.y = fmaf(acc.y, dd, bb.y);
    o.z = fmaf(acc.z, dd, bb.z);
    o.w = fmaf(acc.w, dd, bb.w);
    ((float4*)out)[(size_t)node * F4 + sub] = o;
}

// ===========================================================================
// Tensor-core GEMM (bf16-split, cp.async double-buffered, ldmatrix A):
//   C[M x NOUT] = A[M x K] @ B^T + bias,  B stored [NB x K] (n-major)
// CTA tile 128 x (NWARPN*32); warps: 4 m-warps x NWARPN n-warps.
// grid = (n_col_chunks, m_tiles): x fastest -> same-A CTAs adjacent (L2 reuse)
// smem (dynamic): [AH0 AL0 AH1 AL1 | BH0 BL0 BH1 BL1], row stride 144B.
// ===========================================================================
template <int NWARPN>
__global__ void __launch_bounds__(NWARPN * 128, 1) gemm_mma_k(
    const __nv_bfloat16* __restrict__ Ah, const __nv_bfloat16* __restrict__ Al,
    const __nv_bfloat16* __restrict__ Bh, const __nv_bfloat16* __restrict__ Bl,
    float* __restrict__ C, const float* __restrict__ bias,
    int M, int K, int NOUT)
{
    constexpr int NT   = NWARPN * 128;
    constexpr int NCOL = NWARPN * 32;
    constexpr uint32_t SA_HALF  = 128 * 144;        // 18432
    constexpr uint32_t SA_STAGE = 2 * SA_HALF;
    constexpr uint32_t SB_HALF  = NCOL * 144;
    constexpr uint32_t SB_STAGE = 2 * SB_HALF;
    constexpr uint32_t B0       = 2 * SA_STAGE;     // 73728

    extern __shared__ __align__(16) char smem[];
    const uint32_t sb = smem_u32(smem);

    const int tid  = threadIdx.x;
    const int lane = tid & 31;
    const int wid  = tid >> 5;
    const int mw   = wid & 3;
    const int nw   = wid >> 2;
    const int lq   = lane >> 2;
    const int lr   = lane & 3;
    const int col0 = blockIdx.x * NCOL;
    const int row0 = blockIdx.y * 128;

    float acc[2][4][4];
#pragma unroll
    for (int a = 0; a < 2; a++)
#pragma unroll
        for (int b = 0; b < 4; b++)
#pragma unroll
            for (int c = 0; c < 4; c++) acc[a][b][c] = 0.f;

    auto load_chunk = [&](int stg, int k0) {
        uint32_t ah = sb + stg * SA_STAGE;
        for (int s = tid; s < 1024; s += NT) {
            int r = s >> 3, c = s & 7;
            int gr = row0 + r; if (gr >= M) gr = M - 1;   // clamp; results discarded
            size_t go = ((size_t)gr * K + k0) * 2 + c * 16;
            uint32_t d = ah + r * 144 + c * 16;
            cp16(d, (const char*)Ah + go);
            cp16(d + SA_HALF, (const char*)Al + go);
        }
        uint32_t bh = sb + B0 + stg * SB_STAGE;
        for (int s = tid; s < NCOL * 8; s += NT) {
            int r = s >> 3, c = s & 7;
            size_t go = ((size_t)(col0 + r) * K + k0) * 2 + c * 16;
            uint32_t d = bh + r * 144 + c * 16;
            cp16(d, (const char*)Bh + go);
            cp16(d + SB_HALF, (const char*)Bl + go);
        }
    };

    const int KCH = K >> 6;
    load_chunk(0, 0);
    asm volatile("cp.async.commit_group;");

    for (int ch = 0; ch < KCH; ch++) {
        if (ch + 1 < KCH) load_chunk((ch + 1) & 1, (ch + 1) << 6);
        asm volatile("cp.async.commit_group;");
        asm volatile("cp.async.wait_group %0;" :: "n"(1));
        __syncthreads();

        const uint32_t aH = sb + (ch & 1) * SA_STAGE;
        const uint32_t bH = sb + B0 + (ch & 1) * SB_STAGE;
#pragma unroll
        for (int ks = 0; ks < 4; ks++) {
            const int kk = ks * 16;
            uint32_t ahf[2][4], alf[2][4];
#pragma unroll
            for (int mf = 0; mf < 2; mf++) {
                uint32_t ad = aH + (mw * 32 + mf * 16 + (lane & 15)) * 144
                                 + (kk + ((lane >> 4) << 3)) * 2;
                ldsm4(ahf[mf], ad);
                ldsm4(alf[mf], ad + SA_HALF);
            }
#pragma unroll
            for (int nf = 0; nf < 4; nf++) {
                uint32_t ba = bH + (nw * 32 + nf * 8 + lq) * 144 + (kk + lr * 2) * 2;
                uint32_t bhf[2], blf[2];
                bhf[0] = lds32(ba);           bhf[1] = lds32(ba + 16);
                blf[0] = lds32(ba + SB_HALF); blf[1] = lds32(ba + SB_HALF + 16);
#pragma unroll
                for (int mf = 0; mf < 2; mf++) {
                    mma_bf16(acc[mf][nf], ahf[mf], bhf);   // hh
                    mma_bf16(acc[mf][nf], ahf[mf], blf);   // hl
                    mma_bf16(acc[mf][nf], alf[mf], bhf);   // lh
                }
            }
        }
        __syncthreads();
    }

    // epilogue: + bias, fp32 store (cc even, NOUT even -> float2 safe)
#pragma unroll
    for (int mf = 0; mf < 2; mf++) {
        int r = row0 + mw * 32 + mf * 16 + lq;
#pragma unroll
        for (int nf = 0; nf < 4; nf++) {
            int cc = col0 + nw * 32 + nf * 8 + lr * 2;
            if (cc < NOUT) {
                float2 bb = bias ? *(const float2*)(bias + cc)
                                 : make_float2(0.f, 0.f);
                if (r < M)
                    *(float2*)(C + (size_t)r * NOUT + cc) =
                        make_float2(acc[mf][nf][0] + bb.x, acc[mf][nf][1] + bb.y);
                if (r + 8 < M)
                    *(float2*)(C + (size_t)(r + 8) * NOUT + cc) =
                        make_float2(acc[mf][nf][2] + bb.x, acc[mf][nf][3] + bb.y);
            }
        }
    }
}

// ===========================================================================
// BatchNorm: float partial sums -> double atomics; finalize; apply (+split)
// ===========================================================================
__global__ void zero_stats_k() { g_stats[threadIdx.x] = 0.0; }

__global__ void stats_k(const float* __restrict__ y, int n, int F) {
    int f = threadIdx.x;
    if (f >= F) return;
    float s = 0.f, ss = 0.f;
    for (int r = blockIdx.x; r < n; r += gridDim.x) {
        float v = y[(size_t)r * F + f];
        s += v;
        ss = fmaf(v, v, ss);
    }
    atomicAdd(&g_stats[f], (double)s);
    atomicAdd(&g_stats[F + f], (double)ss);
}

__global__ void finalize_k(const float* __restrict__ gam,
                           const float* __restrict__ bet, int n, int F) {
    int f = threadIdx.x;
    if (f >= F) return;
    double mean = g_stats[f] / (double)n;
    double var  = g_stats[F + f] / (double)n - mean * mean;
    float is = rsqrtf((float)var + 1e-5f);
    float sc = gam[f] * is;
    g_scale[f] = sc;
    g_shift[f] = bet[f] - (float)mean * sc;
}

__global__ void norm_k(const float* __restrict__ y, float* __restrict__ of,
                       __nv_bfloat16* __restrict__ oh, __nv_bfloat16* __restrict__ ol,
                       int F, int do_relu) {
    int node = blockIdx.x;
    for (int f = threadIdx.x; f < F; f += blockDim.x) {
        float v = fmaf(g_scale[f], y[(size_t)node * F + f], g_shift[f]);
        if (do_relu) v = fmaxf(v, 0.0f);
        if (of) of[(size_t)node * F + f] = v;
        if (oh) {
            __nv_bfloat16 h, l;
            split_bf16(v, h, l);
            oh[(size_t)node * F + f] = h;
            ol[(size_t)node * F + f] = l;
        }
    }
}

// ===========================================================================
// host launch
// ===========================================================================
extern "C" void kernel_launch(void* const* d_in, const int* in_sizes, int n_in,
                              void* d_out, int out_size)
{
    const float* x   = (const float*)d_in[0];
    const void*  ei  = d_in[1];
    const float* W1  = (const float*)d_in[2];
    const float* b1  = (const float*)d_in[3];
    const float* ga1 = (const float*)d_in[4];
    const float* be1 = (const float*)d_in[5];
    const float* W2  = (const float*)d_in[6];
    const float* b2  = (const float*)d_in[7];
    const float* ga2 = (const float*)d_in[8];
    const float* be2 = (const float*)d_in[9];
    const float* W3  = (const float*)d_in[10];
    const float* b3  = (const float*)d_in[11];
    const float* ga3 = (const float*)d_in[12];
    const float* be3 = (const float*)d_in[13];

    int n = in_sizes[0] / 128;   // 100000
    int E = in_sizes[1] / 2;     // 800000

    float* out = (float*)d_out;             // [n, 40]
    float* x6  = out + (size_t)n * 40;      // [n, 512]

    __nv_bfloat16 *uh, *ul, *wh, *wl;
    float *hbuf, *tbuf;
    cudaGetSymbolAddress((void**)&uh, g_uh);
    cudaGetSymbolAddress((void**)&ul, g_ul);
    cudaGetSymbolAddress((void**)&wh, g_wh);
    cudaGetSymbolAddress((void**)&wl, g_wl);
    cudaGetSymbolAddress((void**)&hbuf, g_h);
    cudaGetSymbolAddress((void**)&tbuf, g_t);

    const int SMEM4 = 73728 + 2 * 2 * 128 * 144;   // 147456
    const int SMEM2 = 73728 + 2 * 2 * 64 * 144;    // 110592
    cudaFuncSetAttribute(gemm_mma_k<4>,
                         cudaFuncAttributeMaxDynamicSharedMemorySize, SMEM4);
    cudaFuncSetAttribute(gemm_mma_k<2>,
                         cudaFuncAttributeMaxDynamicSharedMemorySize, SMEM2);

    const int T = 256;
    int gbN = (n + T - 1) / T;
    int gbE = (E + T - 1) / T;
    int nb1024 = (n + 1023) / 1024;
    int gtiles = (n + 127) / 128;

    // ---- graph prep ----
    detect_k<<<1, 256>>>((const long long*)ei, (E < 4096 ? E : 4096), n);
    zero_deg_k<<<gbN, T>>>(n);
    hist_k<<<gbE, T>>>(ei, E);
    dinv_k<<<gbN, T>>>(n);
    scan1_k<<<nb1024, 1024>>>(n);
    scan2_k<<<1, 32>>>(nb1024);
    scan3_k<<<gbN, T>>>(n, E);
    fill_k<<<gbE, T>>>(ei, E);

    // ---- Layer 1: agg(x)[128] -> GEMM(K=128,N=512) -> stats ----
    wconv_k<<<(512 * 128 + 255) / 256, 256>>>(W1, 128, 512, 512);
    agg_split_k<32, 4><<<(n + 3) / 4, 128>>>(x, uh, ul, n, 0);
    gemm_mma_k<4><<<dim3(4, gtiles), 512, SMEM4>>>(uh, ul, wh, wl, hbuf, b1,
                                                   n, 128, 512);
    zero_stats_k<<<1, 1024>>>();
    stats_k<<<256, 512>>>(hbuf, n, 512);
    finalize_k<<<1, 512>>>(ga1, be1, n, 512);

    // ---- Layer 2: agg(relu(bn(h1))) fused -> GEMM(K=512,N=512) -> BN -> x6 ----
    wconv_k<<<(512 * 512 + 255) / 256, 256>>>(W2, 512, 512, 512);
    agg_split_k<128, 1><<<n, 128>>>(hbuf, uh, ul, n, 1);
    gemm_mma_k<4><<<dim3(4, gtiles), 512, SMEM4>>>(uh, ul, wh, wl, hbuf, b2,
                                                   n, 512, 512);
    zero_stats_k<<<1, 1024>>>();
    stats_k<<<256, 512>>>(hbuf, n, 512);
    finalize_k<<<1, 512>>>(ga2, be2, n, 512);
    norm_k<<<n, 128>>>(hbuf, x6, uh, ul, 512, 1);

    // ---- Layer 3: GEMM(x6)[K=512,N=40pad64] -> agg(+b3) -> BN -> out ----
    wconv_k<<<(64 * 512 + 255) / 256, 256>>>(W3, 512, 40, 64);
    gemm_mma_k<2><<<dim3(1, gtiles), 256, SMEM2>>>(uh, ul, wh, wl, tbuf, nullptr,
                                                   n, 512, 40);
    agg_f32_k<<<(n + 7) / 8, 128>>>(tbuf, hbuf, b3, n, 10);
    zero_stats_k<<<1, 1024>>>();
    stats_k<<<256, 64>>>(hbuf, n, 40);
    finalize_k<<<1, 64>>>(ga3, be3, n, 40);
    norm_k<<<n, 64>>>(hbuf, out, nullptr, nullptr, 40, 0);
}

// round 15
// speedup vs baseline: 2.1319x; 1.1969x over previous
#include <cuda_runtime.h>
#include <cuda_bf16.h>
#include <cstdint>

// ---------------------------------------------------------------------------
// GCN1: 3x (GCNConv -> BatchNorm -> ReLU[except last]) on N=100000, E=800000
// Output: concat( out[N x 40], x6[N x 512] )
//
// Pipeline (aggregate narrow side; tensor-core bf16-split GEMMs):
//   L1: u = agg(x)[128]            -> h1 = uW1+b1 (GEMM, fused BN stats)
//   L2: u = agg(relu(bn(h1)))[512] -> h2 = uW2+b2 (GEMM, fused BN stats)
//   L3: GEMM A-stage fuses relu(bn(h2)) -> writes x6 AND feeds A operand;
//       h = x6W3 -> y = agg(h)+b3 -> BN -> out
// GEMM numerics: hi/lo bf16 split, acc += Ah*Bh + Ah*Bl + Al*Bh in fp32.
// ---------------------------------------------------------------------------

#define NODES_MAX 100000
#define EDGES_MAX 800000
#define HID 512

// ---- device scratch ----
__device__ __nv_bfloat16 g_uh[NODES_MAX * HID];
__device__ __nv_bfloat16 g_ul[NODES_MAX * HID];
__device__ float  g_h [NODES_MAX * HID];
__device__ float  g_t [NODES_MAX * HID];
__device__ __nv_bfloat16 g_wh[HID * HID];   // transposed: [nb][K]
__device__ __nv_bfloat16 g_wl[HID * HID];
__device__ float  g_dinv[NODES_MAX];
__device__ int    g_deg[NODES_MAX];
__device__ int    g_rowptr[NODES_MAX + 1];
__device__ int    g_cursor[NODES_MAX];
__device__ int    g_csrsrc[EDGES_MAX];
__device__ int    g_bsums[256];
__device__ double g_stats[2 * HID];
__device__ float  g_scale[HID];
__device__ float  g_shift[HID];
__device__ int    g_is64;

__device__ __forceinline__ void split_bf16(float v, __nv_bfloat16& h, __nv_bfloat16& l) {
    h = __float2bfloat16(v);
    l = __float2bfloat16(v - __bfloat162float(h));
}

// mma.sync m16n8k16 bf16 x bf16 -> f32 (sm_80 baseline, compute_103-safe)
__device__ __forceinline__ void mma_bf16(float (&c)[4],
                                         const uint32_t (&a)[4],
                                         const uint32_t (&b)[2]) {
    asm volatile(
        "mma.sync.aligned.m16n8k16.row.col.f32.bf16.bf16.f32 "
        "{%0,%1,%2,%3}, {%4,%5,%6,%7}, {%8,%9}, {%0,%1,%2,%3};"
        : "+f"(c[0]), "+f"(c[1]), "+f"(c[2]), "+f"(c[3])
        : "r"(a[0]), "r"(a[1]), "r"(a[2]), "r"(a[3]), "r"(b[0]), "r"(b[1]));
}
__device__ __forceinline__ uint32_t smem_u32(const void* p) {
    uint32_t a;
    asm("{ .reg .u64 t; cvta.to.shared.u64 t, %1; cvt.u32.u64 %0, t; }"
        : "=r"(a) : "l"(p));
    return a;
}
__device__ __forceinline__ void cp16(uint32_t dst, const void* src) {
    asm volatile("cp.async.cg.shared.global [%0], [%1], 16;"
                 :: "r"(dst), "l"(src));
}
__device__ __forceinline__ void ldsm4(uint32_t (&r)[4], uint32_t addr) {
    asm volatile("ldmatrix.sync.aligned.m8n8.x4.shared.b16 {%0,%1,%2,%3}, [%4];"
                 : "=r"(r[0]), "=r"(r[1]), "=r"(r[2]), "=r"(r[3]) : "r"(addr));
}

// ===========================================================================
// Shared inner loop: one 64-wide K chunk of MMAs.
// A frags via ldmatrix.x4 (row-major), B frags via ldmatrix.x4:
//   lanes 0-7 -> (nf even, kk), 8-15 -> (nf even, kk+8),
//   16-23 -> (nf odd, kk), 24-31 -> (nf odd, kk+8)
// -> regs {b0,b1} for two nf per instruction.
// ===========================================================================
__device__ __forceinline__ void chunk_mma(
    uint32_t aH, uint32_t bH, uint32_t saHalf, uint32_t sbHalf,
    int mw, int nw, int lane, float (&acc)[2][4][4])
{
    const uint32_t a0 = aH + (mw * 32 + (lane & 15)) * 144 + ((lane >> 4) << 4);
    const int g = lane >> 3;
    const uint32_t b0 = bH + (nw * 32 + ((g >> 1) << 3) + (lane & 7)) * 144
                           + ((g & 1) << 4);
#pragma unroll
    for (int ks = 0; ks < 4; ks++) {
        const uint32_t koff = ks * 32;   // 16 bf16 = 32 bytes
        uint32_t ahf[2][4], alf[2][4];
#pragma unroll
        for (int mf = 0; mf < 2; mf++) {
            uint32_t ad = a0 + mf * 16 * 144 + koff;
            ldsm4(ahf[mf], ad);
            ldsm4(alf[mf], ad + saHalf);
        }
        uint32_t bh01[4], bl01[4], bh23[4], bl23[4];
        uint32_t ba = b0 + koff;
        ldsm4(bh01, ba);
        ldsm4(bl01, ba + sbHalf);
        ldsm4(bh23, ba + 16 * 144);
        ldsm4(bl23, ba + 16 * 144 + sbHalf);
#pragma unroll
        for (int nf = 0; nf < 4; nf++) {
            const uint32_t* ph = (nf < 2) ? bh01 : bh23;
            const uint32_t* pl = (nf < 2) ? bl01 : bl23;
            uint32_t bh[2] = {ph[(nf & 1) * 2], ph[(nf & 1) * 2 + 1]};
            uint32_t bl[2] = {pl[(nf & 1) * 2], pl[(nf & 1) * 2 + 1]};
#pragma unroll
            for (int mf = 0; mf < 2; mf++) {
                mma_bf16(acc[mf][nf], ahf[mf], bh);   // hh
                mma_bf16(acc[mf][nf], ahf[mf], bl);   // hl
                mma_bf16(acc[mf][nf], alf[mf], bh);   // lh
            }
        }
    }
}

// ===========================================================================
// Graph prep (CSR by dst, dinv)
// ===========================================================================
__global__ void detect_k(const long long* __restrict__ p, int cnt, int n) {
    __shared__ int bad;
    if (threadIdx.x == 0) bad = 0;
    __syncthreads();
    int loc = 0;
    for (int i = threadIdx.x; i < cnt; i += blockDim.x) {
        long long v = p[i];
        if (v < 0 || v >= (long long)n) loc = 1;
    }
    if (loc) bad = 1;
    __syncthreads();
    if (threadIdx.x == 0) g_is64 = bad ? 0 : 1;
}
__global__ void zero_deg_k(int n) {
    int i = blockIdx.x * blockDim.x + threadIdx.x;
    if (i < n) g_deg[i] = 0;
}
__global__ void hist_k(const void* __restrict__ ei, int E) {
    int e = blockIdx.x * blockDim.x + threadIdx.x;
    if (e >= E) return;
    int d;
    if (g_is64) d = (int)((const long long*)ei)[(size_t)E + e];
    else        d = ((const int*)ei)[(size_t)E + e];
    atomicAdd(&g_deg[d], 1);
}
__global__ void dinv_k(int n) {
    int i = blockIdx.x * blockDim.x + threadIdx.x;
    if (i < n) g_dinv[i] = rsqrtf((float)g_deg[i] + 1.0f);
}
__global__ void scan1_k(int n) {
    __shared__ int sh[1024];
    int tid = threadIdx.x;
    int i = blockIdx.x * 1024 + tid;
    int v = (i < n) ? g_deg[i] : 0;
    sh[tid] = v;
    __syncthreads();
    for (int off = 1; off < 1024; off <<= 1) {
        int t = 0;
        if (tid >= off) t = sh[tid - off];
        __syncthreads();
        sh[tid] += t;
        __syncthreads();
    }
    if (i < n) g_rowptr[i] = sh[tid] - v;
    if (tid == 1023) g_bsums[blockIdx.x] = sh[1023];
}
__global__ void scan2_k(int nb) {
    if (threadIdx.x == 0 && blockIdx.x == 0) {
        int acc = 0;
        for (int i = 0; i < nb; i++) { int t = g_bsums[i]; g_bsums[i] = acc; acc += t; }
    }
}
__global__ void scan3_k(int n, int E) {
    int i = blockIdx.x * blockDim.x + threadIdx.x;
    if (i < n) {
        int r = g_rowptr[i] + g_bsums[i >> 10];
        g_rowptr[i] = r;
        g_cursor[i] = r;
    }
    if (i == 0) g_rowptr[n] = E;
}
__global__ void fill_k(const void* __restrict__ ei, int E) {
    int e = blockIdx.x * blockDim.x + threadIdx.x;
    if (e >= E) return;
    int s, d;
    if (g_is64) {
        const long long* p = (const long long*)ei;
        s = (int)p[e]; d = (int)p[(size_t)E + e];
    } else {
        const int* p = (const int*)ei;
        s = p[e]; d = p[(size_t)E + e];
    }
    int pos = atomicAdd(&g_cursor[d], 1);
    g_csrsrc[pos] = s;
}

// ===========================================================================
// Weight convert: g_wh/g_wl[nb*K+k] = split( W[k*N+nb] ), zero-pad nb>=N
// ===========================================================================
__global__ void wconv_k(const float* __restrict__ W, int K, int N, int NB) {
    int i = blockIdx.x * blockDim.x + threadIdx.x;
    if (i >= NB * K) return;
    int nb = i / K, k = i - nb * K;
    float v = (nb < N) ? W[(size_t)k * N + nb] : 0.0f;
    __nv_bfloat16 h, l;
    split_bf16(v, h, l);
    g_wh[i] = h;
    g_wl[i] = l;
}

// ===========================================================================
// Aggregation (CSR gather), optional fused BN-affine+ReLU on gathered input
// ===========================================================================
__device__ __forceinline__ float4 xform(float4 v, float4 sc, float4 sh, int affine) {
    if (affine) {
        v.x = fmaxf(fmaf(sc.x, v.x, sh.x), 0.f);
        v.y = fmaxf(fmaf(sc.y, v.y, sh.y), 0.f);
        v.z = fmaxf(fmaf(sc.z, v.z, sh.z), 0.f);
        v.w = fmaxf(fmaf(sc.w, v.w, sh.w), 0.f);
    }
    return v;
}

template <int F4, int NPB>
__global__ void agg_split_k(const float* __restrict__ in,
                            __nv_bfloat16* __restrict__ oh,
                            __nv_bfloat16* __restrict__ ol,
                            int n, int affine) {
    int sub  = threadIdx.x & (F4 - 1);
    int node = blockIdx.x * NPB + (threadIdx.x / F4);
    if (node >= n) return;
    const float4* iv = (const float4*)in;
    float4 sc = make_float4(1.f, 1.f, 1.f, 1.f);
    float4 sh = make_float4(0.f, 0.f, 0.f, 0.f);
    if (affine) {
        sc = *(const float4*)(g_scale + sub * 4);
        sh = *(const float4*)(g_shift + sub * 4);
    }
    float dd = g_dinv[node];
    float4 v = xform(__ldg(&iv[(size_t)node * F4 + sub]), sc, sh, affine);
    float4 acc = make_float4(v.x * dd, v.y * dd, v.z * dd, v.w * dd);
    int e = g_rowptr[node], e1 = g_rowptr[node + 1];
    for (; e + 1 < e1; e += 2) {
        int s0 = g_csrsrc[e], s1 = g_csrsrc[e + 1];
        float d0 = g_dinv[s0], d1 = g_dinv[s1];
        float4 v0 = xform(__ldg(&iv[(size_t)s0 * F4 + sub]), sc, sh, affine);
        float4 v1 = xform(__ldg(&iv[(size_t)s1 * F4 + sub]), sc, sh, affine);
        acc.x += v0.x * d0 + v1.x * d1;
        acc.y += v0.y * d0 + v1.y * d1;
        acc.z += v0.z * d0 + v1.z * d1;
        acc.w += v0.w * d0 + v1.w * d1;
    }
    if (e < e1) {
        int s = g_csrsrc[e];
        float ds = g_dinv[s];
        float4 vv = xform(__ldg(&iv[(size_t)s * F4 + sub]), sc, sh, affine);
        acc.x += vv.x * ds; acc.y += vv.y * ds;
        acc.z += vv.z * ds; acc.w += vv.w * ds;
    }
    acc.x *= dd; acc.y *= dd; acc.z *= dd; acc.w *= dd;

    __nv_bfloat16 h0, l0, h1, l1, h2, l2, h3, l3;
    split_bf16(acc.x, h0, l0); split_bf16(acc.y, h1, l1);
    split_bf16(acc.z, h2, l2); split_bf16(acc.w, h3, l3);
    size_t base = ((size_t)node * F4 + sub) * 4;
    uint2 ph, pl;
    ph.x = (uint32_t)__bfloat16_as_ushort(h0) | ((uint32_t)__bfloat16_as_ushort(h1) << 16);
    ph.y = (uint32_t)__bfloat16_as_ushort(h2) | ((uint32_t)__bfloat16_as_ushort(h3) << 16);
    pl.x = (uint32_t)__bfloat16_as_ushort(l0) | ((uint32_t)__bfloat16_as_ushort(l1) << 16);
    pl.y = (uint32_t)__bfloat16_as_ushort(l2) | ((uint32_t)__bfloat16_as_ushort(l3) << 16);
    *(uint2*)(oh + base) = ph;
    *(uint2*)(ol + base) = pl;
}

// L3 aggregation, fp32 + bias. F4=10; 16 threads/node, 8 nodes/block.
__global__ void agg_f32_k(const float* __restrict__ in, float* __restrict__ out,
                          const float* __restrict__ bias, int n, int F4) {
    int sub  = threadIdx.x & 15;
    int node = blockIdx.x * 8 + (threadIdx.x >> 4);
    if (node >= n || sub >= F4) return;
    const float4* iv = (const float4*)in;
    float dd = g_dinv[node];
    float4 sv = __ldg(&iv[(size_t)node * F4 + sub]);
    float4 acc = make_float4(sv.x * dd, sv.y * dd, sv.z * dd, sv.w * dd);
    int e = g_rowptr[node], e1 = g_rowptr[node + 1];
    for (; e < e1; e++) {
        int s = g_csrsrc[e];
        float ds = g_dinv[s];
        float4 v = __ldg(&iv[(size_t)s * F4 + sub]);
        acc.x += v.x * ds; acc.y += v.y * ds; acc.z += v.z * ds; acc.w += v.w * ds;
    }
    float4 bb = __ldg(&((const float4*)bias)[sub]);
    float4 o;
    o.x = fmaf(acc.x, dd, bb.x);
    o.y = fmaf(acc.y, dd, bb.y);
    o.z = fmaf(acc.z, dd, bb.z);
    o.w = fmaf(acc.w, dd, bb.w);
    ((float4*)out)[(size_t)node * F4 + sub] = o;
}

// ===========================================================================
// Main tensor-core GEMM (cp.async double-buffered A+B, ldmatrix frags):
//   C[M x NOUT] = A[M x K] @ B^T + bias; optional fused BN stats (sum, sumsq)
// grid = (n_col_chunks, m_tiles); CTA tile 128 x (NWARPN*32).
// ===========================================================================
template <int NWARPN>
__global__ void __launch_bounds__(NWARPN * 128, 1) gemm_mma_k(
    const __nv_bfloat16* __restrict__ Ah, const __nv_bfloat16* __restrict__ Al,
    const __nv_bfloat16* __restrict__ Bh, const __nv_bfloat16* __restrict__ Bl,
    float* __restrict__ C, const float* __restrict__ bias,
    int M, int K, int NOUT, int do_stats)
{
    constexpr int NT   = NWARPN * 128;
    constexpr int NCOL = NWARPN * 32;
    constexpr uint32_t SA_HALF  = 128 * 144;
    constexpr uint32_t SA_STAGE = 2 * SA_HALF;
    constexpr uint32_t SB_HALF  = NCOL * 144;
    constexpr uint32_t SB_STAGE = 2 * SB_HALF;
    constexpr uint32_t B0       = 2 * SA_STAGE;

    extern __shared__ __align__(16) char smem[];
    const uint32_t sb = smem_u32(smem);

    const int tid  = threadIdx.x;
    const int lane = tid & 31;
    const int wid  = tid >> 5;
    const int mw   = wid & 3;
    const int nw   = wid >> 2;
    const int lq   = lane >> 2;
    const int lr   = lane & 3;
    const int col0 = blockIdx.x * NCOL;
    const int row0 = blockIdx.y * 128;

    float acc[2][4][4];
#pragma unroll
    for (int a = 0; a < 2; a++)
#pragma unroll
        for (int b = 0; b < 4; b++)
#pragma unroll
            for (int c = 0; c < 4; c++) acc[a][b][c] = 0.f;

    auto load_chunk = [&](int stg, int k0) {
        uint32_t ah = sb + stg * SA_STAGE;
        for (int s = tid; s < 1024; s += NT) {
            int r = s >> 3, c = s & 7;
            int gr = row0 + r; if (gr >= M) gr = M - 1;   // clamp; discarded
            size_t go = ((size_t)gr * K + k0) * 2 + c * 16;
            uint32_t d = ah + r * 144 + c * 16;
            cp16(d, (const char*)Ah + go);
            cp16(d + SA_HALF, (const char*)Al + go);
        }
        uint32_t bh = sb + B0 + stg * SB_STAGE;
        for (int s = tid; s < NCOL * 8; s += NT) {
            int r = s >> 3, c = s & 7;
            size_t go = ((size_t)(col0 + r) * K + k0) * 2 + c * 16;
            uint32_t d = bh + r * 144 + c * 16;
            cp16(d, (const char*)Bh + go);
            cp16(d + SB_HALF, (const char*)Bl + go);
        }
    };

    const int KCH = K >> 6;
    load_chunk(0, 0);
    asm volatile("cp.async.commit_group;");

    for (int ch = 0; ch < KCH; ch++) {
        if (ch + 1 < KCH) load_chunk((ch + 1) & 1, (ch + 1) << 6);
        asm volatile("cp.async.commit_group;");
        asm volatile("cp.async.wait_group %0;" :: "n"(1));
        __syncthreads();
        chunk_mma(sb + (ch & 1) * SA_STAGE, sb + B0 + (ch & 1) * SB_STAGE,
                  SA_HALF, SB_HALF, mw, nw, lane, acc);
        __syncthreads();
    }

    // epilogue: + bias, store; optional fused BN stats via shfl + double atomics
#pragma unroll
    for (int nf = 0; nf < 4; nf++) {
        int cc = col0 + nw * 32 + nf * 8 + lr * 2;
        float2 bb = bias ? *(const float2*)(bias + cc) : make_float2(0.f, 0.f);
        float s0 = 0.f, s1 = 0.f, q0 = 0.f, q1 = 0.f;
#pragma unroll
        for (int mf = 0; mf < 2; mf++) {
            int r = row0 + mw * 32 + mf * 16 + lq;
            float v0 = acc[mf][nf][0] + bb.x, v1 = acc[mf][nf][1] + bb.y;
            float v2 = acc[mf][nf][2] + bb.x, v3 = acc[mf][nf][3] + bb.y;
            if (cc < NOUT) {
                if (r < M)
                    *(float2*)(C + (size_t)r * NOUT + cc) = make_float2(v0, v1);
                if (r + 8 < M)
                    *(float2*)(C + (size_t)(r + 8) * NOUT + cc) = make_float2(v2, v3);
            }
            if (do_stats) {
                if (r < M)     { s0 += v0; s1 += v1; q0 += v0 * v0; q1 += v1 * v1; }
                if (r + 8 < M) { s0 += v2; s1 += v3; q0 += v2 * v2; q1 += v3 * v3; }
            }
        }
        if (do_stats) {
#pragma unroll
            for (int o = 4; o < 32; o <<= 1) {
                s0 += __shfl_xor_sync(0xffffffffu, s0, o);
                s1 += __shfl_xor_sync(0xffffffffu, s1, o);
                q0 += __shfl_xor_sync(0xffffffffu, q0, o);
                q1 += __shfl_xor_sync(0xffffffffu, q1, o);
            }
            if ((lane >> 2) == 0 && cc < NOUT) {
                atomicAdd(&g_stats[cc],        (double)s0);
                atomicAdd(&g_stats[cc + 1],    (double)s1);
                atomicAdd(&g_stats[NOUT + cc],     (double)q0);
                atomicAdd(&g_stats[NOUT + cc + 1], (double)q1);
            }
        }
    }
}

// ===========================================================================
// L3 GEMM with fused A generation: reads h2 (hbuf), applies BN affine + ReLU,
// writes x6 (harness output), splits to bf16 smem A operand.
//   C[M x NOUT] = relu(bn(h2)) @ B^T     (K = 512 fixed, NCOL = 64)
// ===========================================================================
__global__ void __launch_bounds__(256, 1) gemm_l3_k(
    const float* __restrict__ hin, float* __restrict__ x6,
    const __nv_bfloat16* __restrict__ Bh, const __nv_bfloat16* __restrict__ Bl,
    float* __restrict__ C, int M, int NOUT)
{
    constexpr int K = 512;
    constexpr uint32_t SA_HALF  = 128 * 144;   // 18432
    constexpr uint32_t SB_HALF  = 64 * 144;    // 9216
    constexpr uint32_t SB_STAGE = 2 * SB_HALF;
    constexpr uint32_t B0       = 2 * SA_HALF; // 36864

    extern __shared__ __align__(16) char smem[];
    const uint32_t sb = smem_u32(smem);

    const int tid  = threadIdx.x;
    const int lane = tid & 31;
    const int wid  = tid >> 5;
    const int mw   = wid & 3;
    const int nw   = wid >> 2;                 // 0..1
    const int lq   = lane >> 2;
    const int lr   = lane & 3;
    const int row0 = blockIdx.x * 128;

    float acc[2][4][4];
#pragma unroll
    for (int a = 0; a < 2; a++)
#pragma unroll
        for (int b = 0; b < 4; b++)
#pragma unroll
            for (int c = 0; c < 4; c++) acc[a][b][c] = 0.f;

    auto load_b = [&](int stg, int k0) {
        uint32_t bh = sb + B0 + stg * SB_STAGE;
        for (int s = tid; s < 512; s += 256) {
            int r = s >> 3, c = s & 7;
            size_t go = ((size_t)r * K + k0) * 2 + c * 16;
            uint32_t d = bh + r * 144 + c * 16;
            cp16(d, (const char*)Bh + go);
            cp16(d + SB_HALF, (const char*)Bl + go);
        }
    };
    load_b(0, 0);
    asm volatile("cp.async.commit_group;");

    for (int ch = 0; ch < 8; ch++) {
        int k0 = ch << 6;
        // stage A: hbuf -> affine+relu -> x6 + split to smem
        for (int s = tid; s < 2048; s += 256) {
            int r = s >> 4, c4 = s & 15;
            int gr = row0 + r;
            float4 v = make_float4(0.f, 0.f, 0.f, 0.f);
            if (gr < M) {
                v = __ldg((const float4*)(hin + (size_t)gr * K + k0 + c4 * 4));
                float4 sc = *(const float4*)(g_scale + k0 + c4 * 4);
                float4 sh = *(const float4*)(g_shift + k0 + c4 * 4);
                v.x = fmaxf(fmaf(sc.x, v.x, sh.x), 0.f);
                v.y = fmaxf(fmaf(sc.y, v.y, sh.y), 0.f);
                v.z = fmaxf(fmaf(sc.z, v.z, sh.z), 0.f);
                v.w = fmaxf(fmaf(sc.w, v.w, sh.w), 0.f);
                *(float4*)(x6 + (size_t)gr * K + k0 + c4 * 4) = v;
            }
            __nv_bfloat16 h0, l0, h1, l1, h2, l2, h3, l3;
            split_bf16(v.x, h0, l0); split_bf16(v.y, h1, l1);
            split_bf16(v.z, h2, l2); split_bf16(v.w, h3, l3);
            uint2 ph, pl;
            ph.x = (uint32_t)__bfloat16_as_ushort(h0) | ((uint32_t)__bfloat16_as_ushort(h1) << 16);
            ph.y = (uint32_t)__bfloat16_as_ushort(h2) | ((uint32_t)__bfloat16_as_ushort(h3) << 16);
            pl.x = (uint32_t)__bfloat16_as_ushort(l0) | ((uint32_t)__bfloat16_as_ushort(l1) << 16);
            pl.y = (uint32_t)__bfloat16_as_ushort(l2) | ((uint32_t)__bfloat16_as_ushort(l3) << 16);
            *(uint2*)(smem + r * 144 + c4 * 8) = ph;
            *(uint2*)(smem + SA_HALF + r * 144 + c4 * 8) = pl;
        }
        if (ch + 1 < 8) load_b((ch + 1) & 1, (ch + 1) << 6);
        asm volatile("cp.async.commit_group;");
        asm volatile("cp.async.wait_group %0;" :: "n"(1));
        __syncthreads();
        chunk_mma(sb, sb + B0 + (ch & 1) * SB_STAGE,
                  SA_HALF, SB_HALF, mw, nw, lane, acc);
        __syncthreads();
    }

    // epilogue (no bias here; added in agg)
#pragma unroll
    for (int mf = 0; mf < 2; mf++) {
        int r = row0 + mw * 32 + mf * 16 + lq;
#pragma unroll
        for (int nf = 0; nf < 4; nf++) {
            int cc = nw * 32 + nf * 8 + lr * 2;
            if (cc < NOUT) {
                if (r < M)
                    *(float2*)(C + (size_t)r * NOUT + cc) =
                        make_float2(acc[mf][nf][0], acc[mf][nf][1]);
                if (r + 8 < M)
                    *(float2*)(C + (size_t)(r + 8) * NOUT + cc) =
                        make_float2(acc[mf][nf][2], acc[mf][nf][3]);
            }
        }
    }
}

// ===========================================================================
// BatchNorm helpers (L3 still uses stats_k; finalize shared by all layers)
// ===========================================================================
__global__ void zero_stats_k() { g_stats[threadIdx.x] = 0.0; }

__global__ void stats_k(const float* __restrict__ y, int n, int F) {
    int f = threadIdx.x;
    if (f >= F) return;
    float s = 0.f, ss = 0.f;
    for (int r = blockIdx.x; r < n; r += gridDim.x) {
        float v = y[(size_t)r * F + f];
        s += v;
        ss = fmaf(v, v, ss);
    }
    atomicAdd(&g_stats[f], (double)s);
    atomicAdd(&g_stats[F + f], (double)ss);
}

__global__ void finalize_k(const float* __restrict__ gam,
                           const float* __restrict__ bet, int n, int F) {
    int f = threadIdx.x;
    if (f >= F) return;
    double mean = g_stats[f] / (double)n;
    double var  = g_stats[F + f] / (double)n - mean * mean;
    float is = rsqrtf((float)var + 1e-5f);
    float sc = gam[f] * is;
    g_scale[f] = sc;
    g_shift[f] = bet[f] - (float)mean * sc;
}

__global__ void norm_k(const float* __restrict__ y, float* __restrict__ of,
                       int F, int do_relu) {
    int node = blockIdx.x;
    for (int f = threadIdx.x; f < F; f += blockDim.x) {
        float v = fmaf(g_scale[f], y[(size_t)node * F + f], g_shift[f]);
        if (do_relu) v = fmaxf(v, 0.0f);
        of[(size_t)node * F + f] = v;
    }
}

// ===========================================================================
// host launch
// ===========================================================================
extern "C" void kernel_launch(void* const* d_in, const int* in_sizes, int n_in,
                              void* d_out, int out_size)
{
    const float* x   = (const float*)d_in[0];
    const void*  ei  = d_in[1];
    const float* W1  = (const float*)d_in[2];
    const float* b1  = (const float*)d_in[3];
    const float* ga1 = (const float*)d_in[4];
    const float* be1 = (const float*)d_in[5];
    const float* W2  = (const float*)d_in[6];
    const float* b2  = (const float*)d_in[7];
    const float* ga2 = (const float*)d_in[8];
    const float* be2 = (const float*)d_in[9];
    const float* W3  = (const float*)d_in[10];
    const float* b3  = (const float*)d_in[11];
    const float* ga3 = (const float*)d_in[12];
    const float* be3 = (const float*)d_in[13];

    int n = in_sizes[0] / 128;   // 100000
    int E = in_sizes[1] / 2;     // 800000

    float* out = (float*)d_out;             // [n, 40]
    float* x6  = out + (size_t)n * 40;      // [n, 512]

    __nv_bfloat16 *uh, *ul, *wh, *wl;
    float *hbuf, *tbuf;
    cudaGetSymbolAddress((void**)&uh, g_uh);
    cudaGetSymbolAddress((void**)&ul, g_ul);
    cudaGetSymbolAddress((void**)&wh, g_wh);
    cudaGetSymbolAddress((void**)&wl, g_wl);
    cudaGetSymbolAddress((void**)&hbuf, g_h);
    cudaGetSymbolAddress((void**)&tbuf, g_t);

    const int SMEM4  = 73728 + 2 * 2 * 128 * 144;   // 147456
    const int SMEML3 = 36864 + 2 * 2 * 64 * 144;    // 73728
    cudaFuncSetAttribute(gemm_mma_k<4>,
                         cudaFuncAttributeMaxDynamicSharedMemorySize, SMEM4);
    cudaFuncSetAttribute(gemm_l3_k,
                         cudaFuncAttributeMaxDynamicSharedMemorySize, SMEML3);

    const int T = 256;
    int gbN = (n + T - 1) / T;
    int gbE = (E + T - 1) / T;
    int nb1024 = (n + 1023) / 1024;
    int gtiles = (n + 127) / 128;

    // ---- graph prep ----
    detect_k<<<1, 256>>>((const long long*)ei, (E < 4096 ? E : 4096), n);
    zero_deg_k<<<gbN, T>>>(n);
    hist_k<<<gbE, T>>>(ei, E);
    dinv_k<<<gbN, T>>>(n);
    scan1_k<<<nb1024, 1024>>>(n);
    scan2_k<<<1, 32>>>(nb1024);
    scan3_k<<<gbN, T>>>(n, E);
    fill_k<<<gbE, T>>>(ei, E);

    // ---- Layer 1: agg(x)[128] -> GEMM(K=128,N=512, fused stats) ----
    wconv_k<<<(512 * 128 + 255) / 256, 256>>>(W1, 128, 512, 512);
    agg_split_k<32, 4><<<(n + 3) / 4, 128>>>(x, uh, ul, n, 0);
    zero_stats_k<<<1, 1024>>>();
    gemm_mma_k<4><<<dim3(4, gtiles), 512, SMEM4>>>(uh, ul, wh, wl, hbuf, b1,
                                                   n, 128, 512, 1);
    finalize_k<<<1, 512>>>(ga1, be1, n, 512);

    // ---- Layer 2: agg(relu(bn(h1))) -> GEMM(K=512,N=512, fused stats) ----
    wconv_k<<<(512 * 512 + 255) / 256, 256>>>(W2, 512, 512, 512);
    agg_split_k<128, 1><<<n, 128>>>(hbuf, uh, ul, n, 1);
    zero_stats_k<<<1, 1024>>>();
    gemm_mma_k<4><<<dim3(4, gtiles), 512, SMEM4>>>(uh, ul, wh, wl, hbuf, b2,
                                                   n, 512, 512, 1);
    finalize_k<<<1, 512>>>(ga2, be2, n, 512);

    // ---- Layer 3: fused (bn+relu+x6-write) GEMM -> agg(+b3) -> BN -> out ----
    wconv_k<<<(64 * 512 + 255) / 256, 256>>>(W3, 512, 40, 64);
    gemm_l3_k<<<gtiles, 256, SMEML3>>>(hbuf, x6, wh, wl, tbuf, n, 40);
    agg_f32_k<<<(n + 7) / 8, 128>>>(tbuf, hbuf, b3, n, 10);
    zero_stats_k<<<1, 1024>>>();
    stats_k<<<256, 64>>>(hbuf, n, 40);
    finalize_k<<<1, 64>>>(ga3, be3, n, 40);
    norm_k<<<n, 64>>>(hbuf, out, 40, 0);
}

// round 16
// speedup vs baseline: 2.5926x; 1.2161x over previous
#include <cuda_runtime.h>
#include <cuda_fp16.h>
#include <cstdint>

// ---------------------------------------------------------------------------
// GCN1: 3x (GCNConv -> BatchNorm -> ReLU[except last]) on N=100000, E=800000
// Output: concat( out[N x 40], x6[N x 512] )
//
// Pipeline (aggregate narrow side; tensor-core fp16x2 GEMMs):
//   L1: u = agg(x)[128]            -> h1 = uW1+b1 (GEMM, fused BN stats)
//   L2: u = agg(relu(bn(h1)))[512] -> h2 = uW2+b2 (GEMM, fused BN stats)
//   L3: GEMM A-stage fuses relu(bn(h2)) -> writes x6 AND feeds A operand;
//       h = x6W3 -> y = agg(h)+b3 -> BN -> out
// GEMM numerics: A single fp16 (err ~2^-12), B fp16 hi+lo;
//   acc += A*Bh + A*Bl in fp32  (2 MMAs; expected final rel_err ~4e-4)
// ---------------------------------------------------------------------------

#define NODES_MAX 100000
#define EDGES_MAX 800000
#define HID 512

// weight region offsets in g_wh/g_wl: W1 [512x128], W2 [512x512], W3 [64x512]
#define WO1 0
#define WO2 65536
#define WO3 327680
#define WTOT 360448

// ---- device scratch ----
__device__ __half  g_ua[NODES_MAX * HID];     // GEMM A operand (fp16)
__device__ float   g_h [NODES_MAX * HID];
__device__ float   g_t [NODES_MAX * HID];
__device__ __half  g_wh[WTOT];                // weights hi (transposed [nb][K])
__device__ __half  g_wl[WTOT];                // weights lo
__device__ float   g_dinv[NODES_MAX];
__device__ int     g_deg[NODES_MAX];
__device__ int     g_rowptr[NODES_MAX + 1];
__device__ int     g_cursor[NODES_MAX];
__device__ int     g_csrsrc[EDGES_MAX];
__device__ int     g_bsums[256];
__device__ double  g_stats[2176];             // L1 [0:1024), L2 [1024:2048), L3 [2048:2176)
__device__ float   g_scale[HID];
__device__ float   g_shift[HID];
__device__ int     g_is64;

__device__ __forceinline__ void split_f16(float v, __half& h, __half& l) {
    h = __float2half_rn(v);
    l = __float2half_rn(v - __half2float(h));
}

// mma.sync m16n8k16 f16 x f16 -> f32 (sm_80 baseline, compute_103-safe)
__device__ __forceinline__ void mma_f16(float (&c)[4],
                                        const uint32_t (&a)[4],
                                        const uint32_t (&b)[2]) {
    asm volatile(
        "mma.sync.aligned.m16n8k16.row.col.f32.f16.f16.f32 "
        "{%0,%1,%2,%3}, {%4,%5,%6,%7}, {%8,%9}, {%0,%1,%2,%3};"
        : "+f"(c[0]), "+f"(c[1]), "+f"(c[2]), "+f"(c[3])
        : "r"(a[0]), "r"(a[1]), "r"(a[2]), "r"(a[3]), "r"(b[0]), "r"(b[1]));
}
__device__ __forceinline__ uint32_t smem_u32(const void* p) {
    uint32_t a;
    asm("{ .reg .u64 t; cvta.to.shared.u64 t, %1; cvt.u32.u64 %0, t; }"
        : "=r"(a) : "l"(p));
    return a;
}
__device__ __forceinline__ void cp16(uint32_t dst, const void* src) {
    asm volatile("cp.async.cg.shared.global [%0], [%1], 16;"
                 :: "r"(dst), "l"(src));
}
__device__ __forceinline__ void ldsm4(uint32_t (&r)[4], uint32_t addr) {
    asm volatile("ldmatrix.sync.aligned.m8n8.x4.shared.b16 {%0,%1,%2,%3}, [%4];"
                 : "=r"(r[0]), "=r"(r[1]), "=r"(r[2]), "=r"(r[3]) : "r"(addr));
}

// ===========================================================================
// Shared inner loop: one 64-wide K chunk. A single fp16, B hi+lo fp16.
// Per (mf,nf): 2 MMAs (A*Bh + A*Bl).
// ===========================================================================
__device__ __forceinline__ void chunk_mma(
    uint32_t aH, uint32_t bH, uint32_t sbHalf,
    int mw, int nw, int lane, float (&acc)[2][4][4])
{
    const uint32_t a0 = aH + (mw * 32 + (lane & 15)) * 144 + ((lane >> 4) << 4);
    const int g = lane >> 3;
    const uint32_t b0 = bH + (nw * 32 + ((g >> 1) << 3) + (lane & 7)) * 144
                           + ((g & 1) << 4);
#pragma unroll
    for (int ks = 0; ks < 4; ks++) {
        const uint32_t koff = ks * 32;   // 16 fp16 = 32 bytes
        uint32_t af[2][4];
#pragma unroll
        for (int mf = 0; mf < 2; mf++)
            ldsm4(af[mf], a0 + mf * 16 * 144 + koff);
        uint32_t bh01[4], bl01[4], bh23[4], bl23[4];
        uint32_t ba = b0 + koff;
        ldsm4(bh01, ba);
        ldsm4(bl01, ba + sbHalf);
        ldsm4(bh23, ba + 16 * 144);
        ldsm4(bl23, ba + 16 * 144 + sbHalf);
#pragma unroll
        for (int nf = 0; nf < 4; nf++) {
            const uint32_t* ph = (nf < 2) ? bh01 : bh23;
            const uint32_t* pl = (nf < 2) ? bl01 : bl23;
            uint32_t bh[2] = {ph[(nf & 1) * 2], ph[(nf & 1) * 2 + 1]};
            uint32_t bl[2] = {pl[(nf & 1) * 2], pl[(nf & 1) * 2 + 1]};
#pragma unroll
            for (int mf = 0; mf < 2; mf++) {
                mma_f16(acc[mf][nf], af[mf], bh);
                mma_f16(acc[mf][nf], af[mf], bl);
            }
        }
    }
}

// ===========================================================================
// Graph prep (CSR by dst, dinv) + stats zeroing
// ===========================================================================
__global__ void prep1_k(const long long* __restrict__ p, int cnt, int n) {
    int i = blockIdx.x * blockDim.x + threadIdx.x;
    if (i < n) g_deg[i] = 0;
    if (i < 2176) g_stats[i] = 0.0;
    if (blockIdx.x == 0) {
        __shared__ int bad;
        if (threadIdx.x == 0) bad = 0;
        __syncthreads();
        int loc = 0;
        for (int j = threadIdx.x; j < cnt; j += blockDim.x) {
            long long v = p[j];
            if (v < 0 || v >= (long long)n) loc = 1;
        }
        if (loc) bad = 1;
        __syncthreads();
        if (threadIdx.x == 0) g_is64 = bad ? 0 : 1;
    }
}
__global__ void hist_k(const void* __restrict__ ei, int E) {
    int e = blockIdx.x * blockDim.x + threadIdx.x;
    if (e >= E) return;
    int d;
    if (g_is64) d = (int)((const long long*)ei)[(size_t)E + e];
    else        d = ((const int*)ei)[(size_t)E + e];
    atomicAdd(&g_deg[d], 1);
}
__global__ void scan1_k(int n) {
    __shared__ int sh[1024];
    int tid = threadIdx.x;
    int i = blockIdx.x * 1024 + tid;
    int v = (i < n) ? g_deg[i] : 0;
    sh[tid] = v;
    __syncthreads();
    for (int off = 1; off < 1024; off <<= 1) {
        int t = 0;
        if (tid >= off) t = sh[tid - off];
        __syncthreads();
        sh[tid] += t;
        __syncthreads();
    }
    if (i < n) g_rowptr[i] = sh[tid] - v;
    if (tid == 1023) g_bsums[blockIdx.x] = sh[1023];
}
__global__ void scan2_k(int nb) {
    if (threadIdx.x == 0 && blockIdx.x == 0) {
        int acc = 0;
        for (int i = 0; i < nb; i++) { int t = g_bsums[i]; g_bsums[i] = acc; acc += t; }
    }
}
__global__ void scan3_k(int n, int E) {
    int i = blockIdx.x * blockDim.x + threadIdx.x;
    if (i < n) {
        int r = g_rowptr[i] + g_bsums[i >> 10];
        g_rowptr[i] = r;
        g_cursor[i] = r;
        g_dinv[i]   = rsqrtf((float)g_deg[i] + 1.0f);
    }
    if (i == 0) g_rowptr[n] = E;
}
__global__ void fill_k(const void* __restrict__ ei, int E) {
    int e = blockIdx.x * blockDim.x + threadIdx.x;
    if (e >= E) return;
    int s, d;
    if (g_is64) {
        const long long* p = (const long long*)ei;
        s = (int)p[e]; d = (int)p[(size_t)E + e];
    } else {
        const int* p = (const int*)ei;
        s = p[e]; d = p[(size_t)E + e];
    }
    int pos = atomicAdd(&g_cursor[d], 1);
    g_csrsrc[pos] = s;
}

// ===========================================================================
// All weight conversions in one kernel (transposed [nb][K], fp16 hi/lo)
// ===========================================================================
__global__ void wconv_all_k(const float* __restrict__ W1,
                            const float* __restrict__ W2,
                            const float* __restrict__ W3) {
    int i = blockIdx.x * blockDim.x + threadIdx.x;
    if (i >= WTOT) return;
    float v;
    if (i < WO2) {                         // W1: [128,512] -> [512][128]
        int j = i - WO1, nb = j >> 7, k = j & 127;
        v = W1[(size_t)k * 512 + nb];
    } else if (i < WO3) {                  // W2: [512,512] -> [512][512]
        int j = i - WO2, nb = j >> 9, k = j & 511;
        v = W2[(size_t)k * 512 + nb];
    } else {                               // W3: [512,40] -> [64][512], pad
        int j = i - WO3, nb = j >> 9, k = j & 511;
        v = (nb < 40) ? W3[(size_t)k * 40 + nb] : 0.0f;
    }
    __half h, l;
    split_f16(v, h, l);
    g_wh[i] = h;
    g_wl[i] = l;
}

// ===========================================================================
// Aggregation (CSR gather), optional fused BN-affine+ReLU on gathered input;
// emits single fp16 A operand.
// ===========================================================================
__device__ __forceinline__ float4 xform(float4 v, float4 sc, float4 sh, int affine) {
    if (affine) {
        v.x = fmaxf(fmaf(sc.x, v.x, sh.x), 0.f);
        v.y = fmaxf(fmaf(sc.y, v.y, sh.y), 0.f);
        v.z = fmaxf(fmaf(sc.z, v.z, sh.z), 0.f);
        v.w = fmaxf(fmaf(sc.w, v.w, sh.w), 0.f);
    }
    return v;
}

template <int F4, int NPB>
__global__ void agg_split_k(const float* __restrict__ in,
                            __half* __restrict__ oa,
                            int n, int affine) {
    int sub  = threadIdx.x & (F4 - 1);
    int node = blockIdx.x * NPB + (threadIdx.x / F4);
    if (node >= n) return;
    const float4* iv = (const float4*)in;
    float4 sc = make_float4(1.f, 1.f, 1.f, 1.f);
    float4 sh = make_float4(0.f, 0.f, 0.f, 0.f);
    if (affine) {
        sc = *(const float4*)(g_scale + sub * 4);
        sh = *(const float4*)(g_shift + sub * 4);
    }
    float dd = g_dinv[node];
    float4 v = xform(__ldg(&iv[(size_t)node * F4 + sub]), sc, sh, affine);
    float4 acc = make_float4(v.x * dd, v.y * dd, v.z * dd, v.w * dd);
    int e = g_rowptr[node], e1 = g_rowptr[node + 1];
    for (; e + 1 < e1; e += 2) {
        int s0 = g_csrsrc[e], s1 = g_csrsrc[e + 1];
        float d0 = g_dinv[s0], d1 = g_dinv[s1];
        float4 v0 = xform(__ldg(&iv[(size_t)s0 * F4 + sub]), sc, sh, affine);
        float4 v1 = xform(__ldg(&iv[(size_t)s1 * F4 + sub]), sc, sh, affine);
        acc.x += v0.x * d0 + v1.x * d1;
        acc.y += v0.y * d0 + v1.y * d1;
        acc.z += v0.z * d0 + v1.z * d1;
        acc.w += v0.w * d0 + v1.w * d1;
    }
    if (e < e1) {
        int s = g_csrsrc[e];
        float ds = g_dinv[s];
        float4 vv = xform(__ldg(&iv[(size_t)s * F4 + sub]), sc, sh, affine);
        acc.x += vv.x * ds; acc.y += vv.y * ds;
        acc.z += vv.z * ds; acc.w += vv.w * ds;
    }
    acc.x *= dd; acc.y *= dd; acc.z *= dd; acc.w *= dd;

    __half2 p0 = __floats2half2_rn(acc.x, acc.y);
    __half2 p1 = __floats2half2_rn(acc.z, acc.w);
    size_t base = ((size_t)node * F4 + sub) * 4;
    uint2 pk;
    pk.x = *(const uint32_t*)&p0;
    pk.y = *(const uint32_t*)&p1;
    *(uint2*)(oa + base) = pk;
}

// L3 aggregation, fp32 + bias. F4=10; 16 threads/node, 8 nodes/block.
__global__ void agg_f32_k(const float* __restrict__ in, float* __restrict__ out,
                          const float* __restrict__ bias, int n, int F4) {
    int sub  = threadIdx.x & 15;
    int node = blockIdx.x * 8 + (threadIdx.x >> 4);
    if (node >= n || sub >= F4) return;
    const float4* iv = (const float4*)in;
    float dd = g_dinv[node];
    float4 sv = __ldg(&iv[(size_t)node * F4 + sub]);
    float4 acc = make_float4(sv.x * dd, sv.y * dd, sv.z * dd, sv.w * dd);
    int e = g_rowptr[node], e1 = g_rowptr[node + 1];
    for (; e < e1; e++) {
        int s = g_csrsrc[e];
        float ds = g_dinv[s];
        float4 v = __ldg(&iv[(size_t)s * F4 + sub]);
        acc.x += v.x * ds; acc.y += v.y * ds; acc.z += v.z * ds; acc.w += v.w * ds;
    }
    float4 bb = __ldg(&((const float4*)bias)[sub]);
    float4 o;
    o.x = fmaf(acc.x, dd, bb.x);
    o.y = fmaf(acc.y, dd, bb.y);
    o.z = fmaf(acc.z, dd, bb.z);
    o.w = fmaf(acc.w, dd, bb.w);
    ((float4*)out)[(size_t)node * F4 + sub] = o;
}

// ===========================================================================
// Main tensor-core GEMM (cp.async double-buffered A+B, ldmatrix frags):
//   C[M x NOUT] = A[M x K] @ B^T + bias; optional fused BN stats into `stats`
// grid = (n_col_chunks, m_tiles); CTA tile 128 x (NWARPN*32).
// smem: [A0 A1 | BH0 BL0 BH1 BL1], A rows 144B (64 fp16 + pad).
// ===========================================================================
template <int NWARPN>
__global__ void __launch_bounds__(NWARPN * 128, 1) gemm_mma_k(
    const __half* __restrict__ A,
    const __half* __restrict__ Bh, const __half* __restrict__ Bl,
    float* __restrict__ C, const float* __restrict__ bias,
    double* __restrict__ stats,
    int M, int K, int NOUT, int do_stats)
{
    constexpr int NT   = NWARPN * 128;
    constexpr int NCOL = NWARPN * 32;
    constexpr uint32_t SA_STAGE = 128 * 144;        // 18432 (single fp16 A)
    constexpr uint32_t SB_HALF  = NCOL * 144;
    constexpr uint32_t SB_STAGE = 2 * SB_HALF;
    constexpr uint32_t B0       = 2 * SA_STAGE;

    extern __shared__ __align__(16) char smem[];
    const uint32_t sb = smem_u32(smem);

    const int tid  = threadIdx.x;
    const int lane = tid & 31;
    const int wid  = tid >> 5;
    const int mw   = wid & 3;
    const int nw   = wid >> 2;
    const int lq   = lane >> 2;
    const int lr   = lane & 3;
    const int col0 = blockIdx.x * NCOL;
    const int row0 = blockIdx.y * 128;

    float acc[2][4][4];
#pragma unroll
    for (int a = 0; a < 2; a++)
#pragma unroll
        for (int b = 0; b < 4; b++)
#pragma unroll
            for (int c = 0; c < 4; c++) acc[a][b][c] = 0.f;

    auto load_chunk = [&](int stg, int k0) {
        uint32_t ah = sb + stg * SA_STAGE;
        for (int s = tid; s < 1024; s += NT) {
            int r = s >> 3, c = s & 7;
            int gr = row0 + r; if (gr >= M) gr = M - 1;   // clamp; discarded
            cp16(ah + r * 144 + c * 16,
                 (const char*)A + ((size_t)gr * K + k0) * 2 + c * 16);
        }
        uint32_t bh = sb + B0 + stg * SB_STAGE;
        for (int s = tid; s < NCOL * 8; s += NT) {
            int r = s >> 3, c = s & 7;
            size_t go = ((size_t)(col0 + r) * K + k0) * 2 + c * 16;
            uint32_t d = bh + r * 144 + c * 16;
            cp16(d, (const char*)Bh + go);
            cp16(d + SB_HALF, (const char*)Bl + go);
        }
    };

    const int KCH = K >> 6;
    load_chunk(0, 0);
    asm volatile("cp.async.commit_group;");

    for (int ch = 0; ch < KCH; ch++) {
        if (ch + 1 < KCH) load_chunk((ch + 1) & 1, (ch + 1) << 6);
        asm volatile("cp.async.commit_group;");
        asm volatile("cp.async.wait_group %0;" :: "n"(1));
        __syncthreads();
        chunk_mma(sb + (ch & 1) * SA_STAGE, sb + B0 + (ch & 1) * SB_STAGE,
                  SB_HALF, mw, nw, lane, acc);
        __syncthreads();
    }

    // epilogue: + bias, store; optional fused BN stats via shfl + double atomics
#pragma unroll
    for (int nf = 0; nf < 4; nf++) {
        int cc = col0 + nw * 32 + nf * 8 + lr * 2;
        float2 bb = bias ? *(const float2*)(bias + cc) : make_float2(0.f, 0.f);
        float s0 = 0.f, s1 = 0.f, q0 = 0.f, q1 = 0.f;
#pragma unroll
        for (int mf = 0; mf < 2; mf++) {
            int r = row0 + mw * 32 + mf * 16 + lq;
            float v0 = acc[mf][nf][0] + bb.x, v1 = acc[mf][nf][1] + bb.y;
            float v2 = acc[mf][nf][2] + bb.x, v3 = acc[mf][nf][3] + bb.y;
            if (cc < NOUT) {
                if (r < M)
                    *(float2*)(C + (size_t)r * NOUT + cc) = make_float2(v0, v1);
                if (r + 8 < M)
                    *(float2*)(C + (size_t)(r + 8) * NOUT + cc) = make_float2(v2, v3);
            }
            if (do_stats) {
                if (r < M)     { s0 += v0; s1 += v1; q0 += v0 * v0; q1 += v1 * v1; }
                if (r + 8 < M) { s0 += v2; s1 += v3; q0 += v2 * v2; q1 += v3 * v3; }
            }
        }
        if (do_stats) {
#pragma unroll
            for (int o = 4; o < 32; o <<= 1) {
                s0 += __shfl_xor_sync(0xffffffffu, s0, o);
                s1 += __shfl_xor_sync(0xffffffffu, s1, o);
                q0 += __shfl_xor_sync(0xffffffffu, q0, o);
                q1 += __shfl_xor_sync(0xffffffffu, q1, o);
            }
            if ((lane >> 2) == 0 && cc < NOUT) {
                atomicAdd(&stats[cc],            (double)s0);
                atomicAdd(&stats[cc + 1],        (double)s1);
                atomicAdd(&stats[NOUT + cc],     (double)q0);
                atomicAdd(&stats[NOUT + cc + 1], (double)q1);
            }
        }
    }
}

// ===========================================================================
// L3 GEMM with fused A generation: reads h2, applies BN affine + ReLU,
// writes x6 (harness output), converts to fp16 smem A operand.
// ===========================================================================
__global__ void __launch_bounds__(256, 1) gemm_l3_k(
    const float* __restrict__ hin, float* __restrict__ x6,
    const __half* __restrict__ Bh, const __half* __restrict__ Bl,
    float* __restrict__ C, int M, int NOUT)
{
    constexpr int K = 512;
    constexpr uint32_t SA = 128 * 144;         // 18432, single stage
    constexpr uint32_t SB_HALF  = 64 * 144;    // 9216
    constexpr uint32_t SB_STAGE = 2 * SB_HALF;
    constexpr uint32_t B0       = SA;

    extern __shared__ __align__(16) char smem[];
    const uint32_t sb = smem_u32(smem);

    const int tid  = threadIdx.x;
    const int lane = tid & 31;
    const int wid  = tid >> 5;
    const int mw   = wid & 3;
    const int nw   = wid >> 2;                 // 0..1
    const int lq   = lane >> 2;
    const int lr   = lane & 3;
    const int row0 = blockIdx.x * 128;

    float acc[2][4][4];
#pragma unroll
    for (int a = 0; a < 2; a++)
#pragma unroll
        for (int b = 0; b < 4; b++)
#pragma unroll
            for (int c = 0; c < 4; c++) acc[a][b][c] = 0.f;

    auto load_b = [&](int stg, int k0) {
        uint32_t bh = sb + B0 + stg * SB_STAGE;
        for (int s = tid; s < 512; s += 256) {
            int r = s >> 3, c = s & 7;
            size_t go = ((size_t)r * K + k0) * 2 + c * 16;
            uint32_t d = bh + r * 144 + c * 16;
            cp16(d, (const char*)Bh + go);
            cp16(d + SB_HALF, (const char*)Bl + go);
        }
    };
    load_b(0, 0);
    asm volatile("cp.async.commit_group;");

    for (int ch = 0; ch < 8; ch++) {
        int k0 = ch << 6;
        // stage A: hin -> affine+relu -> x6 + fp16 to smem
        for (int s = tid; s < 2048; s += 256) {
            int r = s >> 4, c4 = s & 15;
            int gr = row0 + r;
            float4 v = make_float4(0.f, 0.f, 0.f, 0.f);
            if (gr < M) {
                v = __ldg((const float4*)(hin + (size_t)gr * K + k0 + c4 * 4));
                float4 sc = *(const float4*)(g_scale + k0 + c4 * 4);
                float4 sh = *(const float4*)(g_shift + k0 + c4 * 4);
                v.x = fmaxf(fmaf(sc.x, v.x, sh.x), 0.f);
                v.y = fmaxf(fmaf(sc.y, v.y, sh.y), 0.f);
                v.z = fmaxf(fmaf(sc.z, v.z, sh.z), 0.f);
                v.w = fmaxf(fmaf(sc.w, v.w, sh.w), 0.f);
                *(float4*)(x6 + (size_t)gr * K + k0 + c4 * 4) = v;
            }
            __half2 p0 = __floats2half2_rn(v.x, v.y);
            __half2 p1 = __floats2half2_rn(v.z, v.w);
            uint2 pk;
            pk.x = *(const uint32_t*)&p0;
            pk.y = *(const uint32_t*)&p1;
            *(uint2*)(smem + r * 144 + c4 * 8) = pk;
        }
        if (ch + 1 < 8) load_b((ch + 1) & 1, (ch + 1) << 6);
        asm volatile("cp.async.commit_group;");
        asm volatile("cp.async.wait_group %0;" :: "n"(1));
        __syncthreads();
        chunk_mma(sb, sb + B0 + (ch & 1) * SB_STAGE,
                  SB_HALF, mw, nw, lane, acc);
        __syncthreads();
    }

    // epilogue (no bias; added in agg)
#pragma unroll
    for (int mf = 0; mf < 2; mf++) {
        int r = row0 + mw * 32 + mf * 16 + lq;
#pragma unroll
        for (int nf = 0; nf < 4; nf++) {
            int cc = nw * 32 + nf * 8 + lr * 2;
            if (cc < NOUT) {
                if (r < M)
                    *(float2*)(C + (size_t)r * NOUT + cc) =
                        make_float2(acc[mf][nf][0], acc[mf][nf][1]);
                if (r + 8 < M)
                    *(float2*)(C + (size_t)(r + 8) * NOUT + cc) =
                        make_float2(acc[mf][nf][2], acc[mf][nf][3]);
            }
        }
    }
}

// ===========================================================================
// BatchNorm helpers
// ===========================================================================
__global__ void stats_k(const float* __restrict__ y, double* __restrict__ stats,
                        int n, int F) {
    int f = threadIdx.x;
    if (f >= F) return;
    float s = 0.f, ss = 0.f;
    for (int r = blockIdx.x; r < n; r += gridDim.x) {
        float v = y[(size_t)r * F + f];
        s += v;
        ss = fmaf(v, v, ss);
    }
    atomicAdd(&stats[f], (double)s);
    atomicAdd(&stats[F + f], (double)ss);
}

__global__ void finalize_k(const double* __restrict__ stats,
                           const float* __restrict__ gam,
                           const float* __restrict__ bet, int n, int F) {
    int f = threadIdx.x;
    if (f >= F) return;
    double mean = stats[f] / (double)n;
    double var  = stats[F + f] / (double)n - mean * mean;
    float is = rsqrtf((float)var + 1e-5f);
    float sc = gam[f] * is;
    g_scale[f] = sc;
    g_shift[f] = bet[f] - (float)mean * sc;
}

// grid-stride final output norm (no relu), F = 40
__global__ void normout_k(const float* __restrict__ y, float* __restrict__ o,
                          int total, int F) {
    for (int idx = blockIdx.x * blockDim.x + threadIdx.x; idx < total;
         idx += gridDim.x * blockDim.x) {
        int f = idx % F;
        o[idx] = fmaf(g_scale[f], y[idx], g_shift[f]);
    }
}

// ===========================================================================
// host launch
// ===========================================================================
extern "C" void kernel_launch(void* const* d_in, const int* in_sizes, int n_in,
                              void* d_out, int out_size)
{
    const float* x   = (const float*)d_in[0];
    const void*  ei  = d_in[1];
    const float* W1  = (const float*)d_in[2];
    const float* b1  = (const float*)d_in[3];
    const float* ga1 = (const float*)d_in[4];
    const float* be1 = (const float*)d_in[5];
    const float* W2  = (const float*)d_in[6];
    const float* b2  = (const float*)d_in[7];
    const float* ga2 = (const float*)d_in[8];
    const float* be2 = (const float*)d_in[9];
    const float* W3  = (const float*)d_in[10];
    const float* b3  = (const float*)d_in[11];
    const float* ga3 = (const float*)d_in[12];
    const float* be3 = (const float*)d_in[13];

    int n = in_sizes[0] / 128;   // 100000
    int E = in_sizes[1] / 2;     // 800000

    float* out = (float*)d_out;             // [n, 40]
    float* x6  = out + (size_t)n * 40;      // [n, 512]

    __half *ua, *wh, *wl;
    float *hbuf, *tbuf;
    double* stats;
    cudaGetSymbolAddress((void**)&ua, g_ua);
    cudaGetSymbolAddress((void**)&wh, g_wh);
    cudaGetSymbolAddress((void**)&wl, g_wl);
    cudaGetSymbolAddress((void**)&hbuf, g_h);
    cudaGetSymbolAddress((void**)&tbuf, g_t);
    cudaGetSymbolAddress((void**)&stats, g_stats);

    const int SMEM4  = 36864 + 2 * 2 * 128 * 144;   // 110592
    const int SMEML3 = 18432 + 2 * 2 * 64 * 144;    // 55296
    cudaFuncSetAttribute(gemm_mma_k<4>,
                         cudaFuncAttributeMaxDynamicSharedMemorySize, SMEM4);
    cudaFuncSetAttribute(gemm_l3_k,
                         cudaFuncAttributeMaxDynamicSharedMemorySize, SMEML3);

    const int T = 256;
    int gbN = (n + T - 1) / T;
    int gbE = (E + T - 1) / T;
    int nb1024 = (n + 1023) / 1024;
    int gtiles = (n + 127) / 128;

    // ---- graph prep (also zeros all stats regions) ----
    prep1_k<<<gbN, T>>>((const long long*)ei, (E < 4096 ? E : 4096), n);
    hist_k<<<gbE, T>>>(ei, E);
    scan1_k<<<nb1024, 1024>>>(n);
    scan2_k<<<1, 32>>>(nb1024);
    scan3_k<<<gbN, T>>>(n, E);
    fill_k<<<gbE, T>>>(ei, E);
    wconv_all_k<<<(WTOT + 255) / 256, 256>>>(W1, W2, W3);

    // ---- Layer 1: agg(x)[128] -> GEMM(K=128,N=512, fused stats L1) ----
    agg_split_k<32, 4><<<(n + 3) / 4, 128>>>(x, ua, n, 0);
    gemm_mma_k<4><<<dim3(4, gtiles), 512, SMEM4>>>(ua, wh + WO1, wl + WO1,
                                                   hbuf, b1, stats,
                                                   n, 128, 512, 1);
    finalize_k<<<1, 512>>>(stats, ga1, be1, n, 512);

    // ---- Layer 2: agg(relu(bn(h1))) -> GEMM(K=512,N=512, fused stats L2) ----
    agg_split_k<128, 1><<<n, 128>>>(hbuf, ua, n, 1);
    gemm_mma_k<4><<<dim3(4, gtiles), 512, SMEM4>>>(ua, wh + WO2, wl + WO2,
                                                   hbuf, b2, stats + 1024,
                                                   n, 512, 512, 1);
    finalize_k<<<1, 512>>>(stats + 1024, ga2, be2, n, 512);

    // ---- Layer 3: fused (bn+relu+x6) GEMM -> agg(+b3) -> BN -> out ----
    gemm_l3_k<<<gtiles, 256, SMEML3>>>(hbuf, x6, wh + WO3, wl + WO3,
                                       tbuf, n, 40);
    agg_f32_k<<<(n + 7) / 8, 128>>>(tbuf, hbuf, b3, n, 10);
    stats_k<<<256, 64>>>(hbuf, stats + 2048, n, 40);
    finalize_k<<<1, 64>>>(stats + 2048, ga3, be3, n, 40);
    normout_k<<<1024, 256>>>(hbuf, out, n * 40, 40);
}

// round 17
// speedup vs baseline: 2.6339x; 1.0159x over previous
#include <cuda_runtime.h>
#include <cuda_fp16.h>
#include <cstdint>

// ---------------------------------------------------------------------------
// GCN1: 3x (GCNConv -> BatchNorm -> ReLU[except last]) on N=100000, E=800000
// Output: concat( out[N x 40], x6[N x 512] )
//
// Pipeline (aggregate narrow side; tensor-core fp16x2 GEMMs):
//   L1: u = agg(x)[128]            -> h1 = uW1+b1 (GEMM, fused BN stats)
//   L2: u = agg(relu(bn(h1)))[512] -> h2 = uW2+b2 (GEMM, fused BN stats)
//       (agg done in 2 feature-chunked passes for L2-cache residency)
//   L3: GEMM A-stage fuses relu(bn(h2)) -> writes x6 AND feeds A operand;
//       h = x6W3 -> y = agg(h)+b3 (fused stats) -> BN -> out
// GEMM numerics: A single fp16, B fp16 hi+lo; acc += A*Bh + A*Bl in fp32.
// ---------------------------------------------------------------------------

#define NODES_MAX 100000
#define EDGES_MAX 800000
#define HID 512

// weight region offsets in g_wh/g_wl: W1 [512x128], W2 [512x512], W3 [64x512]
#define WO1 0
#define WO2 65536
#define WO3 327680
#define WTOT 360448

// ---- device scratch ----
__device__ __half  g_ua[NODES_MAX * HID];     // GEMM A operand (fp16)
__device__ float   g_h [NODES_MAX * HID];
__device__ float   g_t [NODES_MAX * HID];
__device__ __half  g_wh[WTOT];                // weights hi (transposed [nb][K])
__device__ __half  g_wl[WTOT];                // weights lo
__device__ float   g_dinv[NODES_MAX];
__device__ int     g_deg[NODES_MAX];
__device__ int     g_rowptr[NODES_MAX + 1];
__device__ int     g_cursor[NODES_MAX];
__device__ int     g_csrsrc[EDGES_MAX];
__device__ int     g_bsums[256];
__device__ double  g_stats[2176];             // L1 [0:1024), L2 [1024:2048), L3 [2048:2176)
__device__ float   g_scale[HID];
__device__ float   g_shift[HID];
__device__ int     g_is64;

__device__ __forceinline__ void split_f16(float v, __half& h, __half& l) {
    h = __float2half_rn(v);
    l = __float2half_rn(v - __half2float(h));
}

// mma.sync m16n8k16 f16 x f16 -> f32 (sm_80 baseline, compute_103-safe)
__device__ __forceinline__ void mma_f16(float (&c)[4],
                                        const uint32_t (&a)[4],
                                        const uint32_t (&b)[2]) {
    asm volatile(
        "mma.sync.aligned.m16n8k16.row.col.f32.f16.f16.f32 "
        "{%0,%1,%2,%3}, {%4,%5,%6,%7}, {%8,%9}, {%0,%1,%2,%3};"
        : "+f"(c[0]), "+f"(c[1]), "+f"(c[2]), "+f"(c[3])
        : "r"(a[0]), "r"(a[1]), "r"(a[2]), "r"(a[3]), "r"(b[0]), "r"(b[1]));
}
__device__ __forceinline__ uint32_t smem_u32(const void* p) {
    uint32_t a;
    asm("{ .reg .u64 t; cvta.to.shared.u64 t, %1; cvt.u32.u64 %0, t; }"
        : "=r"(a) : "l"(p));
    return a;
}
__device__ __forceinline__ void cp16(uint32_t dst, const void* src) {
    asm volatile("cp.async.cg.shared.global [%0], [%1], 16;"
                 :: "r"(dst), "l"(src));
}
__device__ __forceinline__ void ldsm4(uint32_t (&r)[4], uint32_t addr) {
    asm volatile("ldmatrix.sync.aligned.m8n8.x4.shared.b16 {%0,%1,%2,%3}, [%4];"
                 : "=r"(r[0]), "=r"(r[1]), "=r"(r[2]), "=r"(r[3]) : "r"(addr));
}
// streaming store (evict-first): keeps write-once data out of L2's way
__device__ __forceinline__ void stcs_u2(void* p, uint2 v) {
    asm volatile("st.global.cs.v2.u32 [%0], {%1, %2};"
                 :: "l"(p), "r"(v.x), "r"(v.y));
}

// ===========================================================================
// Shared inner loop: one 64-wide K chunk. A single fp16, B hi+lo fp16.
// ===========================================================================
__device__ __forceinline__ void chunk_mma(
    uint32_t aH, uint32_t bH, uint32_t sbHalf,
    int mw, int nw, int lane, float (&acc)[2][4][4])
{
    const uint32_t a0 = aH + (mw * 32 + (lane & 15)) * 144 + ((lane >> 4) << 4);
    const int g = lane >> 3;
    const uint32_t b0 = bH + (nw * 32 + ((g >> 1) << 3) + (lane & 7)) * 144
                           + ((g & 1) << 4);
#pragma unroll
    for (int ks = 0; ks < 4; ks++) {
        const uint32_t koff = ks * 32;   // 16 fp16 = 32 bytes
        uint32_t af[2][4];
#pragma unroll
        for (int mf = 0; mf < 2; mf++)
            ldsm4(af[mf], a0 + mf * 16 * 144 + koff);
        uint32_t bh01[4], bl01[4], bh23[4], bl23[4];
        uint32_t ba = b0 + koff;
        ldsm4(bh01, ba);
        ldsm4(bl01, ba + sbHalf);
        ldsm4(bh23, ba + 16 * 144);
        ldsm4(bl23, ba + 16 * 144 + sbHalf);
#pragma unroll
        for (int nf = 0; nf < 4; nf++) {
            const uint32_t* ph = (nf < 2) ? bh01 : bh23;
            const uint32_t* pl = (nf < 2) ? bl01 : bl23;
            uint32_t bh[2] = {ph[(nf & 1) * 2], ph[(nf & 1) * 2 + 1]};
            uint32_t bl[2] = {pl[(nf & 1) * 2], pl[(nf & 1) * 2 + 1]};
#pragma unroll
            for (int mf = 0; mf < 2; mf++) {
                mma_f16(acc[mf][nf], af[mf], bh);
                mma_f16(acc[mf][nf], af[mf], bl);
            }
        }
    }
}

// ===========================================================================
// prep1: deg-zero + stats-zero + dtype-detect + ALL weight conversions
// (grid = WTOT/256 = 1408 blocks; all work items independent)
// ===========================================================================
__global__ void prep1_k(const long long* __restrict__ p, int cnt, int n,
                        const float* __restrict__ W1,
                        const float* __restrict__ W2,
                        const float* __restrict__ W3) {
    int i = blockIdx.x * blockDim.x + threadIdx.x;
    if (i < n) g_deg[i] = 0;
    if (i < 2176) g_stats[i] = 0.0;

    if (i < WTOT) {
        float v;
        if (i < WO2) {                         // W1: [128,512] -> [512][128]
            int j = i - WO1, nb = j >> 7, k = j & 127;
            v = W1[(size_t)k * 512 + nb];
        } else if (i < WO3) {                  // W2: [512,512] -> [512][512]
            int j = i - WO2, nb = j >> 9, k = j & 511;
            v = W2[(size_t)k * 512 + nb];
        } else {                               // W3: [512,40] -> [64][512], pad
            int j = i - WO3, nb = j >> 9, k = j & 511;
            v = (nb < 40) ? W3[(size_t)k * 40 + nb] : 0.0f;
        }
        __half h, l;
        split_f16(v, h, l);
        g_wh[i] = h;
        g_wl[i] = l;
    }

    if (blockIdx.x == 0) {
        __shared__ int bad;
        if (threadIdx.x == 0) bad = 0;
        __syncthreads();
        int loc = 0;
        for (int j = threadIdx.x; j < cnt; j += blockDim.x) {
            long long v = p[j];
            if (v < 0 || v >= (long long)n) loc = 1;
        }
        if (loc) bad = 1;
        __syncthreads();
        if (threadIdx.x == 0) g_is64 = bad ? 0 : 1;
    }
}
__global__ void hist_k(const void* __restrict__ ei, int E) {
    int e = blockIdx.x * blockDim.x + threadIdx.x;
    if (e >= E) return;
    int d;
    if (g_is64) d = (int)((const long long*)ei)[(size_t)E + e];
    else        d = ((const int*)ei)[(size_t)E + e];
    atomicAdd(&g_deg[d], 1);
}
__global__ void scan1_k(int n) {
    __shared__ int sh[1024];
    int tid = threadIdx.x;
    int i = blockIdx.x * 1024 + tid;
    int v = (i < n) ? g_deg[i] : 0;
    sh[tid] = v;
    __syncthreads();
    for (int off = 1; off < 1024; off <<= 1) {
        int t = 0;
        if (tid >= off) t = sh[tid - off];
        __syncthreads();
        sh[tid] += t;
        __syncthreads();
    }
    if (i < n) g_rowptr[i] = sh[tid] - v;
    if (tid == 1023) g_bsums[blockIdx.x] = sh[1023];
}
// parallel exclusive scan of block sums (nb <= 128)
__global__ void scan2_k(int nb) {
    __shared__ int sh[128];
    int t = threadIdx.x;
    int v = (t < nb) ? g_bsums[t] : 0;
    sh[t] = v;
    __syncthreads();
    for (int off = 1; off < 128; off <<= 1) {
        int u = (t >= off) ? sh[t - off] : 0;
        __syncthreads();
        sh[t] += u;
        __syncthreads();
    }
    if (t < nb) g_bsums[t] = sh[t] - v;   // exclusive
}
__global__ void scan3_k(int n, int E) {
    int i = blockIdx.x * blockDim.x + threadIdx.x;
    if (i < n) {
        int r = g_rowptr[i] + g_bsums[i >> 10];
        g_rowptr[i] = r;
        g_cursor[i] = r;
        g_dinv[i]   = rsqrtf((float)g_deg[i] + 1.0f);
    }
    if (i == 0) g_rowptr[n] = E;
}
__global__ void fill_k(const void* __restrict__ ei, int E) {
    int e = blockIdx.x * blockDim.x + threadIdx.x;
    if (e >= E) return;
    int s, d;
    if (g_is64) {
        const long long* p = (const long long*)ei;
        s = (int)p[e]; d = (int)p[(size_t)E + e];
    } else {
        const int* p = (const int*)ei;
        s = p[e]; d = p[(size_t)E + e];
    }
    int pos = atomicAdd(&g_cursor[d], 1);
    g_csrsrc[pos] = s;
}

// ===========================================================================
// Aggregation (CSR gather), optional fused BN-affine+ReLU; feature-chunked:
// handles float4-columns [foff4, foff4+F4) of a row of F4TOT float4s.
// Emits fp16 A operand via streaming stores.
// ===========================================================================
__device__ __forceinline__ float4 xform(float4 v, float4 sc, float4 sh, int affine) {
    if (affine) {
        v.x = fmaxf(fmaf(sc.x, v.x, sh.x), 0.f);
        v.y = fmaxf(fmaf(sc.y, v.y, sh.y), 0.f);
        v.z = fmaxf(fmaf(sc.z, v.z, sh.z), 0.f);
        v.w = fmaxf(fmaf(sc.w, v.w, sh.w), 0.f);
    }
    return v;
}

template <int F4, int NPB>
__global__ void agg_split_k(const float* __restrict__ in,
                            __half* __restrict__ oa,
                            int n, int affine, int foff4, int F4TOT) {
    int sub  = threadIdx.x & (F4 - 1);
    int node = blockIdx.x * NPB + (threadIdx.x / F4);
    if (node >= n) return;
    int fc = foff4 + sub;
    const float4* iv = (const float4*)in;
    float4 sc = make_float4(1.f, 1.f, 1.f, 1.f);
    float4 sh = make_float4(0.f, 0.f, 0.f, 0.f);
    if (affine) {
        sc = *(const float4*)(g_scale + fc * 4);
        sh = *(const float4*)(g_shift + fc * 4);
    }
    float dd = g_dinv[node];
    float4 v = xform(__ldg(&iv[(size_t)node * F4TOT + fc]), sc, sh, affine);
    float4 acc = make_float4(v.x * dd, v.y * dd, v.z * dd, v.w * dd);
    int e = g_rowptr[node], e1 = g_rowptr[node + 1];
    for (; e + 1 < e1; e += 2) {
        int s0 = g_csrsrc[e], s1 = g_csrsrc[e + 1];
        float d0 = g_dinv[s0], d1 = g_dinv[s1];
        float4 v0 = xform(__ldg(&iv[(size_t)s0 * F4TOT + fc]), sc, sh, affine);
        float4 v1 = xform(__ldg(&iv[(size_t)s1 * F4TOT + fc]), sc, sh, affine);
        acc.x += v0.x * d0 + v1.x * d1;
        acc.y += v0.y * d0 + v1.y * d1;
        acc.z += v0.z * d0 + v1.z * d1;
        acc.w += v0.w * d0 + v1.w * d1;
    }
    if (e < e1) {
        int s = g_csrsrc[e];
        float ds = g_dinv[s];
        float4 vv = xform(__ldg(&iv[(size_t)s * F4TOT + fc]), sc, sh, affine);
        acc.x += vv.x * ds; acc.y += vv.y * ds;
        acc.z += vv.z * ds; acc.w += vv.w * ds;
    }
    acc.x *= dd; acc.y *= dd; acc.z *= dd; acc.w *= dd;

    __half2 p0 = __floats2half2_rn(acc.x, acc.y);
    __half2 p1 = __floats2half2_rn(acc.z, acc.w);
    uint2 pk;
    pk.x = *(const uint32_t*)&p0;
    pk.y = *(const uint32_t*)&p1;
    stcs_u2(oa + ((size_t)node * F4TOT + fc) * 4, pk);
}

// L3 aggregation, fp32 + bias, FUSED BN stats (shared float -> double atomics).
// F4=10; 16 threads/node, 8 nodes/block; stats layout: [0:40) sum, [40:80) sq.
__global__ void agg_f32_k(const float* __restrict__ in, float* __restrict__ out,
                          const float* __restrict__ bias,
                          double* __restrict__ stats, int n, int F4) {
    __shared__ float ss[80];
    int tid = threadIdx.x;
    if (tid < 80) ss[tid] = 0.f;
    __syncthreads();

    int sub  = tid & 15;
    int node = blockIdx.x * 8 + (tid >> 4);
    if (node < n && sub < F4) {
        const float4* iv = (const float4*)in;
        float dd = g_dinv[node];
        float4 sv = __ldg(&iv[(size_t)node * F4 + sub]);
        float4 acc = make_float4(sv.x * dd, sv.y * dd, sv.z * dd, sv.w * dd);
        int e = g_rowptr[node], e1 = g_rowptr[node + 1];
        for (; e < e1; e++) {
            int s = g_csrsrc[e];
            float ds = g_dinv[s];
            float4 v = __ldg(&iv[(size_t)s * F4 + sub]);
            acc.x += v.x * ds; acc.y += v.y * ds;
            acc.z += v.z * ds; acc.w += v.w * ds;
        }
        float4 bb = __ldg(&((const float4*)bias)[sub]);
        float4 o;
        o.x = fmaf(acc.x, dd, bb.x);
        o.y = fmaf(acc.y, dd, bb.y);
        o.z = fmaf(acc.z, dd, bb.z);
        o.w = fmaf(acc.w, dd, bb.w);
        ((float4*)out)[(size_t)node * F4 + sub] = o;
        int f = sub * 4;
        atomicAdd(&ss[f + 0], o.x); atomicAdd(&ss[40 + f + 0], o.x * o.x);
        atomicAdd(&ss[f + 1], o.y); atomicAdd(&ss[40 + f + 1], o.y * o.y);
        atomicAdd(&ss[f + 2], o.z); atomicAdd(&ss[40 + f + 2], o.z * o.z);
        atomicAdd(&ss[f + 3], o.w); atomicAdd(&ss[40 + f + 3], o.w * o.w);
    }
    __syncthreads();
    if (tid < 80) atomicAdd(&stats[tid], (double)ss[tid]);
}

// ===========================================================================
// Main tensor-core GEMM (cp.async double-buffered A+B, ldmatrix frags):
//   C[M x NOUT] = A[M x K] @ B^T + bias; optional fused BN stats into `stats`
// ===========================================================================
template <int NWARPN>
__global__ void __launch_bounds__(NWARPN * 128, 1) gemm_mma_k(
    const __half* __restrict__ A,
    const __half* __restrict__ Bh, const __half* __restrict__ Bl,
    float* __restrict__ C, const float* __restrict__ bias,
    double* __restrict__ stats,
    int M, int K, int NOUT, int do_stats)
{
    constexpr int NT   = NWARPN * 128;
    constexpr int NCOL = NWARPN * 32;
    constexpr uint32_t SA_STAGE = 128 * 144;
    constexpr uint32_t SB_HALF  = NCOL * 144;
    constexpr uint32_t SB_STAGE = 2 * SB_HALF;
    constexpr uint32_t B0       = 2 * SA_STAGE;

    extern __shared__ __align__(16) char smem[];
    const uint32_t sb = smem_u32(smem);

    const int tid  = threadIdx.x;
    const int lane = tid & 31;
    const int wid  = tid >> 5;
    const int mw   = wid & 3;
    const int nw   = wid >> 2;
    const int lq   = lane >> 2;
    const int lr   = lane & 3;
    const int col0 = blockIdx.x * NCOL;
    const int row0 = blockIdx.y * 128;

    float acc[2][4][4];
#pragma unroll
    for (int a = 0; a < 2; a++)
#pragma unroll
        for (int b = 0; b < 4; b++)
#pragma unroll
            for (int c = 0; c < 4; c++) acc[a][b][c] = 0.f;

    auto load_chunk = [&](int stg, int k0) {
        uint32_t ah = sb + stg * SA_STAGE;
        for (int s = tid; s < 1024; s += NT) {
            int r = s >> 3, c = s & 7;
            int gr = row0 + r; if (gr >= M) gr = M - 1;   // clamp; discarded
            cp16(ah + r * 144 + c * 16,
                 (const char*)A + ((size_t)gr * K + k0) * 2 + c * 16);
        }
        uint32_t bh = sb + B0 + stg * SB_STAGE;
        for (int s = tid; s < NCOL * 8; s += NT) {
            int r = s >> 3, c = s & 7;
            size_t go = ((size_t)(col0 + r) * K + k0) * 2 + c * 16;
            uint32_t d = bh + r * 144 + c * 16;
            cp16(d, (const char*)Bh + go);
            cp16(d + SB_HALF, (const char*)Bl + go);
        }
    };

    const int KCH = K >> 6;
    load_chunk(0, 0);
    asm volatile("cp.async.commit_group;");

    for (int ch = 0; ch < KCH; ch++) {
        if (ch + 1 < KCH) load_chunk((ch + 1) & 1, (ch + 1) << 6);
        asm volatile("cp.async.commit_group;");
        asm volatile("cp.async.wait_group %0;" :: "n"(1));
        __syncthreads();
        chunk_mma(sb + (ch & 1) * SA_STAGE, sb + B0 + (ch & 1) * SB_STAGE,
                  SB_HALF, mw, nw, lane, acc);
        __syncthreads();
    }

#pragma unroll
    for (int nf = 0; nf < 4; nf++) {
        int cc = col0 + nw * 32 + nf * 8 + lr * 2;
        float2 bb = bias ? *(const float2*)(bias + cc) : make_float2(0.f, 0.f);
        float s0 = 0.f, s1 = 0.f, q0 = 0.f, q1 = 0.f;
#pragma unroll
        for (int mf = 0; mf < 2; mf++) {
            int r = row0 + mw * 32 + mf * 16 + lq;
            float v0 = acc[mf][nf][0] + bb.x, v1 = acc[mf][nf][1] + bb.y;
            float v2 = acc[mf][nf][2] + bb.x, v3 = acc[mf][nf][3] + bb.y;
            if (cc < NOUT) {
                if (r < M)
                    *(float2*)(C + (size_t)r * NOUT + cc) = make_float2(v0, v1);
                if (r + 8 < M)
                    *(float2*)(C + (size_t)(r + 8) * NOUT + cc) = make_float2(v2, v3);
            }
            if (do_stats) {
                if (r < M)     { s0 += v0; s1 += v1; q0 += v0 * v0; q1 += v1 * v1; }
                if (r + 8 < M) { s0 += v2; s1 += v3; q0 += v2 * v2; q1 += v3 * v3; }
            }
        }
        if (do_stats) {
#pragma unroll
            for (int o = 4; o < 32; o <<= 1) {
                s0 += __shfl_xor_sync(0xffffffffu, s0, o);
                s1 += __shfl_xor_sync(0xffffffffu, s1, o);
                q0 += __shfl_xor_sync(0xffffffffu, q0, o);
                q1 += __shfl_xor_sync(0xffffffffu, q1, o);
            }
            if ((lane >> 2) == 0 && cc < NOUT) {
                atomicAdd(&stats[cc],            (double)s0);
                atomicAdd(&stats[cc + 1],        (double)s1);
                atomicAdd(&stats[NOUT + cc],     (double)q0);
                atomicAdd(&stats[NOUT + cc + 1], (double)q1);
            }
        }
    }
}

// ===========================================================================
// L3 GEMM with fused A generation: reads h2, applies BN affine + ReLU,
// writes x6 (harness output), converts to fp16 smem A operand.
// ===========================================================================
__global__ void __launch_bounds__(256, 1) gemm_l3_k(
    const float* __restrict__ hin, float* __restrict__ x6,
    const __half* __restrict__ Bh, const __half* __restrict__ Bl,
    float* __restrict__ C, int M, int NOUT)
{
    constexpr int K = 512;
    constexpr uint32_t SA = 128 * 144;
    constexpr uint32_t SB_HALF  = 64 * 144;
    constexpr uint32_t SB_STAGE = 2 * SB_HALF;
    constexpr uint32_t B0       = SA;

    extern __shared__ __align__(16) char smem[];
    const uint32_t sb = smem_u32(smem);

    const int tid  = threadIdx.x;
    const int lane = tid & 31;
    const int wid  = tid >> 5;
    const int mw   = wid & 3;
    const int nw   = wid >> 2;                 // 0..1
    const int lq   = lane >> 2;
    const int lr   = lane & 3;
    const int row0 = blockIdx.x * 128;

    float acc[2][4][4];
#pragma unroll
    for (int a = 0; a < 2; a++)
#pragma unroll
        for (int b = 0; b < 4; b++)
#pragma unroll
            for (int c = 0; c < 4; c++) acc[a][b][c] = 0.f;

    auto load_b = [&](int stg, int k0) {
        uint32_t bh = sb + B0 + stg * SB_STAGE;
        for (int s = tid; s < 512; s += 256) {
            int r = s >> 3, c = s & 7;
            size_t go = ((size_t)r * K + k0) * 2 + c * 16;
            uint32_t d = bh + r * 144 + c * 16;
            cp16(d, (const char*)Bh + go);
            cp16(d + SB_HALF, (const char*)Bl + go);
        }
    };
    load_b(0, 0);
    asm volatile("cp.async.commit_group;");

    for (int ch = 0; ch < 8; ch++) {
        int k0 = ch << 6;
        for (int s = tid; s < 2048; s += 256) {
            int r = s >> 4, c4 = s & 15;
            int gr = row0 + r;
            float4 v = make_float4(0.f, 0.f, 0.f, 0.f);
            if (gr < M) {
                v = __ldg((const float4*)(hin + (size_t)gr * K + k0 + c4 * 4));
                float4 sc = *(const float4*)(g_scale + k0 + c4 * 4);
                float4 sh = *(const float4*)(g_shift + k0 + c4 * 4);
                v.x = fmaxf(fmaf(sc.x, v.x, sh.x), 0.f);
                v.y = fmaxf(fmaf(sc.y, v.y, sh.y), 0.f);
                v.z = fmaxf(fmaf(sc.z, v.z, sh.z), 0.f);
                v.w = fmaxf(fmaf(sc.w, v.w, sh.w), 0.f);
                *(float4*)(x6 + (size_t)gr * K + k0 + c4 * 4) = v;
            }
            __half2 p0 = __floats2half2_rn(v.x, v.y);
            __half2 p1 = __floats2half2_rn(v.z, v.w);
            uint2 pk;
            pk.x = *(const uint32_t*)&p0;
            pk.y = *(const uint32_t*)&p1;
            *(uint2*)(smem + r * 144 + c4 * 8) = pk;
        }
        if (ch + 1 < 8) load_b((ch + 1) & 1, (ch + 1) << 6);
        asm volatile("cp.async.commit_group;");
        asm volatile("cp.async.wait_group %0;" :: "n"(1));
        __syncthreads();
        chunk_mma(sb, sb + B0 + (ch & 1) * SB_STAGE,
                  SB_HALF, mw, nw, lane, acc);
        __syncthreads();
    }

#pragma unroll
    for (int mf = 0; mf < 2; mf++) {
        int r = row0 + mw * 32 + mf * 16 + lq;
#pragma unroll
        for (int nf = 0; nf < 4; nf++) {
            int cc = nw * 32 + nf * 8 + lr * 2;
            if (cc < NOUT) {
                if (r < M)
                    *(float2*)(C + (size_t)r * NOUT + cc) =
                        make_float2(acc[mf][nf][0], acc[mf][nf][1]);
                if (r + 8 < M)
                    *(float2*)(C + (size_t)(r + 8) * NOUT + cc) =
                        make_float2(acc[mf][nf][2], acc[mf][nf][3]);
            }
        }
    }
}

// ===========================================================================
// BatchNorm finalize + final output norm
// ===========================================================================
__global__ void finalize_k(const double* __restrict__ stats,
                           const float* __restrict__ gam,
                           const float* __restrict__ bet, int n, int F) {
    int f = threadIdx.x;
    if (f >= F) return;
    double mean = stats[f] / (double)n;
    double var  = stats[F + f] / (double)n - mean * mean;
    float is = rsqrtf((float)var + 1e-5f);
    float sc = gam[f] * is;
    g_scale[f] = sc;
    g_shift[f] = bet[f] - (float)mean * sc;
}

__global__ void normout_k(const float* __restrict__ y, float* __restrict__ o,
                          int total, int F) {
    for (int idx = blockIdx.x * blockDim.x + threadIdx.x; idx < total;
         idx += gridDim.x * blockDim.x) {
        int f = idx % F;
        o[idx] = fmaf(g_scale[f], y[idx], g_shift[f]);
    }
}

// ===========================================================================
// host launch
// ===========================================================================
extern "C" void kernel_launch(void* const* d_in, const int* in_sizes, int n_in,
                              void* d_out, int out_size)
{
    const float* x   = (const float*)d_in[0];
    const void*  ei  = d_in[1];
    const float* W1  = (const float*)d_in[2];
    const float* b1  = (const float*)d_in[3];
    const float* ga1 = (const float*)d_in[4];
    const float* be1 = (const float*)d_in[5];
    const float* W2  = (const float*)d_in[6];
    const float* b2  = (const float*)d_in[7];
    const float* ga2 = (const float*)d_in[8];
    const float* be2 = (const float*)d_in[9];
    const float* W3  = (const float*)d_in[10];
    const float* b3  = (const float*)d_in[11];
    const float* ga3 = (const float*)d_in[12];
    const float* be3 = (const float*)d_in[13];

    int n = in_sizes[0] / 128;   // 100000
    int E = in_sizes[1] / 2;     // 800000

    float* out = (float*)d_out;             // [n, 40]
    float* x6  = out + (size_t)n * 40;      // [n, 512]

    __half *ua, *wh, *wl;
    float *hbuf, *tbuf;
    double* stats;
    cudaGetSymbolAddress((void**)&ua, g_ua);
    cudaGetSymbolAddress((void**)&wh, g_wh);
    cudaGetSymbolAddress((void**)&wl, g_wl);
    cudaGetSymbolAddress((void**)&hbuf, g_h);
    cudaGetSymbolAddress((void**)&tbuf, g_t);
    cudaGetSymbolAddress((void**)&stats, g_stats);

    const int SMEM4  = 36864 + 2 * 2 * 128 * 144;   // 110592
    const int SMEML3 = 18432 + 2 * 2 * 64 * 144;    // 55296
    cudaFuncSetAttribute(gemm_mma_k<4>,
                         cudaFuncAttributeMaxDynamicSharedMemorySize, SMEM4);
    cudaFuncSetAttribute(gemm_l3_k,
                         cudaFuncAttributeMaxDynamicSharedMemorySize, SMEML3);

    const int T = 256;
    int gbN = (n + T - 1) / T;
    int gbE = (E + T - 1) / T;
    int nb1024 = (n + 1023) / 1024;
    int gtiles = (n + 127) / 128;

    // ---- graph prep (merged zero/detect/wconv), CSR build ----
    prep1_k<<<WTOT / 256, 256>>>((const long long*)ei, (E < 4096 ? E : 4096),
                                 n, W1, W2, W3);
    hist_k<<<gbE, T>>>(ei, E);
    scan1_k<<<nb1024, 1024>>>(n);
    scan2_k<<<1, 128>>>(nb1024);
    scan3_k<<<gbN, T>>>(n, E);
    fill_k<<<gbE, T>>>(ei, E);

    // ---- Layer 1: agg(x)[128] -> GEMM(K=128,N=512, fused stats L1) ----
    agg_split_k<32, 4><<<(n + 3) / 4, 128>>>(x, ua, n, 0, 0, 32);
    gemm_mma_k<4><<<dim3(4, gtiles), 512, SMEM4>>>(ua, wh + WO1, wl + WO1,
                                                   hbuf, b1, stats,
                                                   n, 128, 512, 1);
    finalize_k<<<1, 512>>>(stats, ga1, be1, n, 512);

    // ---- Layer 2: agg(relu(bn(h1))) in 2 L2-resident passes -> GEMM ----
    agg_split_k<64, 2><<<(n + 1) / 2, 128>>>(hbuf, ua, n, 1, 0, 128);
    agg_split_k<64, 2><<<(n + 1) / 2, 128>>>(hbuf, ua, n, 1, 64, 128);
    gemm_mma_k<4><<<dim3(4, gtiles), 512, SMEM4>>>(ua, wh + WO2, wl + WO2,
                                                   hbuf, b2, stats + 1024,
                                                   n, 512, 512, 1);
    finalize_k<<<1, 512>>>(stats + 1024, ga2, be2, n, 512);

    // ---- Layer 3: fused (bn+relu+x6) GEMM -> agg(+b3, fused stats) -> out ----
    gemm_l3_k<<<gtiles, 256, SMEML3>>>(hbuf, x6, wh + WO3, wl + WO3,
                                       tbuf, n, 40);
    agg_f32_k<<<(n + 7) / 8, 128>>>(tbuf, hbuf, b3, stats + 2048, n, 10);
    finalize_k<<<1, 64>>>(stats + 2048, ga3, be3, n, 40);
    normout_k<<<1024, 256>>>(hbuf, out, n * 40, 40);
}